// round 5
// baseline (speedup 1.0000x reference)
#include <cuda_runtime.h>
#include <cstdint>
#include <math.h>

#define B_    8
#define NPT   8192
#define MPT   2048
#define C_    256
#define H_    512
#define NTOT  (B_*NPT)

// ---------------- scratch ----------------
__device__ float g_X[(size_t)NTOT * H_];          // [p][perm16(k)] layer-1 input (tf32)
__device__ float g_Y[(size_t)NTOT * H_];          // [p][perm16(o)] layer-1 output (tf32)
__device__ float g_kft[(size_t)B_ * MPT * C_];    // known_feats transposed [b][m][c]
__device__ float g_W1r[H_ * H_];                  // tf32, k-permuted cols
__device__ float g_W2r[H_ * H_];
__device__ int   g_idx[NTOT * 3];
__device__ float g_w[NTOT * 3];

__device__ __forceinline__ float tf32r(float x) {
    asm("cvt.rna.tf32.f32 %0, %1;" : "=f"(x) : "f"(x));
    return x;
}
// 16-group k-permutation: pos = (k%4)*4 + (k/4)%4  (dot-product invariant; applied to ALL k operands)
__device__ __forceinline__ int perm16(int k) {
    return (k & ~15) | ((k & 3) << 2) | ((k >> 2) & 3);
}
__device__ __forceinline__ void cp16(void* s, const void* g) {
    uint32_t a;
    asm("{ .reg .u64 t; cvta.to.shared.u64 t, %1; cvt.u32.u64 %0, t; }" : "=r"(a) : "l"(s));
    asm volatile("cp.async.cg.shared.global [%0], [%1], 16;\n" :: "r"(a), "l"(g));
}

// ---------------- fused prep: round_w (1024 blks) + tr_kf (4096) + tr_uf (16384) ----------------
__global__ __launch_bounds__(256)
void prep_kernel(const float* __restrict__ W1, const float* __restrict__ W2,
                 const float* __restrict__ kf, const float* __restrict__ uf)
{
    __shared__ float t[32][33];
    const int bid = blockIdx.x;
    const int tid = threadIdx.x;

    if (bid < 1024) {
        int i = bid * 256 + tid;
        int o = i >> 9, k = i & 511;
        g_W1r[o * H_ + perm16(k)] = tf32r(W1[i]);
        g_W2r[o * H_ + perm16(k)] = tf32r(W2[i]);
        return;
    }
    const int x = tid & 31, y0 = tid >> 5;
    if (bid < 1024 + 4096) {
        const int idx = bid - 1024;                    // grid (64, 8, 8)
        const int m0 = (idx & 63) * 32;
        const int c0 = ((idx >> 6) & 7) * 32;
        const int b  = idx >> 9;
        #pragma unroll
        for (int yy = 0; yy < 32; yy += 8)
            t[y0+yy][x] = kf[((size_t)b*C_ + c0+y0+yy)*MPT + m0 + x];
        __syncthreads();
        #pragma unroll
        for (int yy = 0; yy < 32; yy += 8)
            g_kft[((size_t)b*MPT + m0 + y0+yy)*C_ + c0 + x] = t[x][y0+yy];
    } else {
        const int idx = bid - 1024 - 4096;             // grid (256, 8, 8)
        const int j0 = (idx & 255) * 32;
        const int c0 = ((idx >> 8) & 7) * 32;
        const int b  = idx >> 11;
        #pragma unroll
        for (int yy = 0; yy < 32; yy += 8)
            t[y0+yy][x] = uf[((size_t)b*C_ + c0+y0+yy)*NPT + j0 + x];
        __syncthreads();
        #pragma unroll
        for (int yy = 0; yy < 32; yy += 8)
            g_X[((size_t)b*NPT + j0 + y0+yy)*H_ + C_ + perm16(c0 + x)] = tf32r(t[x][y0+yy]);
    }
}

// ---------------- 3-NN + weights ----------------
__global__ __launch_bounds__(256)
void knn_kernel(const float* __restrict__ unknown, const float* __restrict__ known)
{
    __shared__ float kx[MPT], ky[MPT], kz[MPT];
    const int b = blockIdx.y;
    const float* kb = known + (size_t)b * MPT * 3;
    for (int i = threadIdx.x; i < MPT; i += 256) {
        kx[i] = kb[i*3+0]; ky[i] = kb[i*3+1]; kz[i] = kb[i*3+2];
    }
    __syncthreads();

    const int q = blockIdx.x * 256 + threadIdx.x;
    const float* up = unknown + ((size_t)b * NPT + q) * 3;
    const float ux = up[0], uy = up[1], uz = up[2];

    float d0 = 1e30f, d1 = 1e30f, d2 = 1e30f;
    int   i0 = 0,     i1 = 0,     i2 = 0;
    #pragma unroll 4
    for (int i = 0; i < MPT; i++) {
        float dx = kx[i]-ux, dy = ky[i]-uy, dz = kz[i]-uz;
        float d = dx*dx + dy*dy + dz*dz;
        if (d < d2) {
            if (d < d1) {
                if (d < d0) { d2=d1; i2=i1; d1=d0; i1=i0; d0=d; i0=i; }
                else        { d2=d1; i2=i1; d1=d;  i1=i; }
            } else          { d2=d;  i2=i; }
        }
    }
    const float r0 = 1.f/(d0+1e-8f), r1 = 1.f/(d1+1e-8f), r2 = 1.f/(d2+1e-8f);
    const float s = 1.f/(r0+r1+r2);
    const int gi = b * NPT + q;
    g_idx[gi*3+0] = i0; g_idx[gi*3+1] = i1; g_idx[gi*3+2] = i2;
    g_w[gi*3+0] = r0*s; g_w[gi*3+1] = r1*s; g_w[gi*3+2] = r2*s;
}

// ---------------- interpolate -> X[p][perm16(0..255)] (tf32); warp per point ----------------
__global__ __launch_bounds__(256)
void interp_kernel()
{
    const int p = blockIdx.x * 8 + (threadIdx.x >> 5);
    const int lane = threadIdx.x & 31;
    const int b = p >> 13;

    const int   i0 = g_idx[p*3+0], i1 = g_idx[p*3+1], i2 = g_idx[p*3+2];
    const float w0 = g_w[p*3+0],   w1 = g_w[p*3+1],   w2 = g_w[p*3+2];

    const float* r0 = g_kft + ((size_t)b*MPT + i0)*C_ + lane*8;
    const float* r1 = g_kft + ((size_t)b*MPT + i1)*C_ + lane*8;
    const float* r2 = g_kft + ((size_t)b*MPT + i2)*C_ + lane*8;

    float4 a0 = *(const float4*)r0, a1 = *(const float4*)(r0+4);
    float4 c0 = *(const float4*)r1, c1 = *(const float4*)(r1+4);
    float4 e0 = *(const float4*)r2, e1 = *(const float4*)(r2+4);

    float lo[4], hi[4];
    lo[0] = tf32r(w0*a0.x + w1*c0.x + w2*e0.x);
    lo[1] = tf32r(w0*a0.y + w1*c0.y + w2*e0.y);
    lo[2] = tf32r(w0*a0.z + w1*c0.z + w2*e0.z);
    lo[3] = tf32r(w0*a0.w + w1*c0.w + w2*e0.w);
    hi[0] = tf32r(w0*a1.x + w1*c1.x + w2*e1.x);
    hi[1] = tf32r(w0*a1.y + w1*c1.y + w2*e1.y);
    hi[2] = tf32r(w0*a1.z + w1*c1.z + w2*e1.z);
    hi[3] = tf32r(w0*a1.w + w1*c1.w + w2*e1.w);

    // channels c = lane*8 + t (t<4 -> lo) / +4 (hi). perm16: float2(lo[t],hi[t])
    // lands at 16*(lane>>1) + 4*t + 2*(lane&1).
    float* xp = g_X + (size_t)p*H_ + 16*(lane >> 1) + 2*(lane & 1);
    #pragma unroll
    for (int t = 0; t < 4; t++) {
        float2 v = make_float2(lo[t], hi[t]);
        *(float2*)(xp + 4*t) = v;
    }
}

// ---------------- tf32 mma.sync GEMM: BM=128, BN=256, BK=32, warp 64x64 ----------------
#define LDT     48                         // row stride floats (pad 16): conflict-free LDS.128
#define A_F     (128*LDT)
#define B_F     (256*LDT)
#define STAGE_F (A_F + B_F)                // 18432 floats (73728 B)
#define NSTAGE  3
#define SMEMB   (NSTAGE*STAGE_F*4)         // 221184 B

__device__ __forceinline__ void mma_tf32(float* c, uint32_t a0, uint32_t a1, uint32_t a2, uint32_t a3,
                                         uint32_t b0, uint32_t b1)
{
    asm volatile(
        "mma.sync.aligned.m16n8k8.row.col.f32.tf32.tf32.f32 "
        "{%0,%1,%2,%3}, {%4,%5,%6,%7}, {%8,%9}, {%0,%1,%2,%3};"
        : "+f"(c[0]), "+f"(c[1]), "+f"(c[2]), "+f"(c[3])
        : "r"(a0), "r"(a1), "r"(a2), "r"(a3), "r"(b0), "r"(b1));
}

__device__ __forceinline__ void load_stage(const float* __restrict__ A, const float* __restrict__ Xn,
                                           int m0, int n0, int kt, float* st, int tid)
{
    const int k0 = kt * 32;
    float* sA = st;
    float* sB = st + A_F;
    #pragma unroll
    for (int i = 0; i < 4; i++) {
        int idx = tid + i*256;
        int row = idx >> 3;
        int c   = idx & 7;
        cp16(sA + row*LDT + c*4, A + (size_t)(m0 + row)*H_ + k0 + c*4);
    }
    #pragma unroll
    for (int i = 0; i < 8; i++) {
        int idx = tid + i*256;
        int row = idx >> 3;
        int c   = idx & 7;
        cp16(sB + row*LDT + c*4, Xn + (size_t)(n0 + row)*H_ + k0 + c*4);
    }
    asm volatile("cp.async.commit_group;\n");
}

__global__ __launch_bounds__(256, 1)
void gemm_tc(const float* __restrict__ A, const float* __restrict__ Xn, float* __restrict__ Out,
             const float* __restrict__ G, const float* __restrict__ Bb,
             const float* __restrict__ Mu, const float* __restrict__ Va, int mode)
{
    extern __shared__ float sm[];
    const int tid  = threadIdx.x;
    const int wid  = tid >> 5;
    const int lane = tid & 31;
    const int g    = lane >> 2;
    const int ctib = lane & 3;
    const int wm0  = (wid >> 2) * 64;
    const int wn0  = (wid & 3)  * 64;
    const int n0   = blockIdx.x * 256;
    const int m0   = blockIdx.y * 128;

    float acc[4][8][4];
    #pragma unroll
    for (int mt = 0; mt < 4; mt++)
        #pragma unroll
        for (int nt = 0; nt < 8; nt++)
            #pragma unroll
            for (int q = 0; q < 4; q++) acc[mt][nt][q] = 0.0f;

    load_stage(A, Xn, m0, n0, 0, sm, tid);
    load_stage(A, Xn, m0, n0, 1, sm + STAGE_F, tid);
    load_stage(A, Xn, m0, n0, 2, sm + 2*STAGE_F, tid);

    for (int kt = 0; kt < 16; kt++) {
        if (kt <= 13)      asm volatile("cp.async.wait_group 2;\n");
        else if (kt == 14) asm volatile("cp.async.wait_group 1;\n");
        else               asm volatile("cp.async.wait_group 0;\n");
        __syncthreads();

        const float* sA = sm + (kt % NSTAGE) * STAGE_F;
        const float* sB = sA + A_F;

        // two 16-k halves; each LDS.128 carries fragments for TWO kk-steps
        #pragma unroll
        for (int kh = 0; kh < 2; kh++) {
            const int off = kh*16 + ctib*4;
            float4 a4lo[4], a4hi[4];
            #pragma unroll
            for (int mt = 0; mt < 4; mt++) {
                a4lo[mt] = *(const float4*)(sA + (wm0 + mt*16 + g    )*LDT + off);
                a4hi[mt] = *(const float4*)(sA + (wm0 + mt*16 + g + 8)*LDT + off);
            }
            float4 b4[8];
            #pragma unroll
            for (int nt = 0; nt < 8; nt++)
                b4[nt] = *(const float4*)(sB + (wn0 + nt*8 + g)*LDT + off);

            #pragma unroll
            for (int mt = 0; mt < 4; mt++)
                #pragma unroll
                for (int nt = 0; nt < 8; nt++)
                    mma_tf32(acc[mt][nt],
                             __float_as_uint(a4lo[mt].x), __float_as_uint(a4hi[mt].x),
                             __float_as_uint(a4lo[mt].y), __float_as_uint(a4hi[mt].y),
                             __float_as_uint(b4[nt].x),   __float_as_uint(b4[nt].y));
            #pragma unroll
            for (int mt = 0; mt < 4; mt++)
                #pragma unroll
                for (int nt = 0; nt < 8; nt++)
                    mma_tf32(acc[mt][nt],
                             __float_as_uint(a4lo[mt].z), __float_as_uint(a4hi[mt].z),
                             __float_as_uint(a4lo[mt].w), __float_as_uint(a4hi[mt].w),
                             __float_as_uint(b4[nt].z),   __float_as_uint(b4[nt].w));
        }
        __syncthreads();
        if (kt + 3 < 16)
            load_stage(A, Xn, m0, n0, kt + 3, sm + (kt % NSTAGE) * STAGE_F, tid);
    }

    // -------- epilogue: BN + ReLU, staged through smem --------
    __syncthreads();
    float* patch = sm + wid * 4224;        // 64*66 floats per warp

    if (mode == 0) {
        // patch [n][m] 64x64; m positions perm16-permuted (Y feeds layer-2 as k)
        #pragma unroll
        for (int mt = 0; mt < 4; mt++) {
            const int o0 = m0 + wm0 + mt*16 + g;
            const float sc0 = G[o0]   * rsqrtf(Va[o0]   + 1e-5f);
            const float sh0 = Bb[o0]   - Mu[o0]  * sc0;
            const float sc1 = G[o0+8] * rsqrtf(Va[o0+8] + 1e-5f);
            const float sh1 = Bb[o0+8] - Mu[o0+8] * sc1;
            const int ml  = perm16(mt*16 + g);
            const int mlh = perm16(mt*16 + g + 8);
            #pragma unroll
            for (int nt = 0; nt < 8; nt++) {
                const int nl = nt*8 + 2*ctib;
                patch[ nl   *66 + ml ] = tf32r(fmaxf(fmaf(acc[mt][nt][0], sc0, sh0), 0.f));
                patch[(nl+1)*66 + ml ] = tf32r(fmaxf(fmaf(acc[mt][nt][1], sc0, sh0), 0.f));
                patch[ nl   *66 + mlh] = tf32r(fmaxf(fmaf(acc[mt][nt][2], sc1, sh1), 0.f));
                patch[(nl+1)*66 + mlh] = tf32r(fmaxf(fmaf(acc[mt][nt][3], sc1, sh1), 0.f));
            }
        }
        __syncwarp();
        float* yb = Out + (size_t)(n0 + wn0) * H_ + m0 + wm0;
        #pragma unroll
        for (int r = 0; r < 64; r++)
            *(float2*)(yb + (size_t)r * H_ + lane*2) = *(float2*)(patch + r*66 + lane*2);
    } else {
        // patch [m][n] 64x64, physical layout
        #pragma unroll
        for (int mt = 0; mt < 4; mt++) {
            const int o0 = m0 + wm0 + mt*16 + g;
            const float sc0 = G[o0]   * rsqrtf(Va[o0]   + 1e-5f);
            const float sh0 = Bb[o0]   - Mu[o0]  * sc0;
            const float sc1 = G[o0+8] * rsqrtf(Va[o0+8] + 1e-5f);
            const float sh1 = Bb[o0+8] - Mu[o0+8] * sc1;
            const int ml = mt*16 + g;
            #pragma unroll
            for (int nt = 0; nt < 8; nt++) {
                const int nl = nt*8 + 2*ctib;
                patch[ ml   *66 + nl  ] = fmaxf(fmaf(acc[mt][nt][0], sc0, sh0), 0.f);
                patch[ ml   *66 + nl+1] = fmaxf(fmaf(acc[mt][nt][1], sc0, sh0), 0.f);
                patch[(ml+8)*66 + nl  ] = fmaxf(fmaf(acc[mt][nt][2], sc1, sh1), 0.f);
                patch[(ml+8)*66 + nl+1] = fmaxf(fmaf(acc[mt][nt][3], sc1, sh1), 0.f);
            }
        }
        __syncwarp();
        const int b  = n0 >> 13;
        const int j0 = (n0 & (NPT-1)) + wn0;
        float* ob = Out + ((size_t)b * H_ + m0 + wm0) * NPT + j0;
        #pragma unroll
        for (int r = 0; r < 64; r++)
            *(float2*)(ob + (size_t)r * NPT + lane*2) = *(float2*)(patch + r*66 + lane*2);
    }
}

// ---------------- launch ----------------
extern "C" void kernel_launch(void* const* d_in, const int* in_sizes, int n_in,
                              void* d_out, int out_size)
{
    const float* unknown      = (const float*)d_in[0];
    const float* known        = (const float*)d_in[1];
    const float* unknow_feats = (const float*)d_in[2];
    const float* known_feats  = (const float*)d_in[3];
    const float* W1 = (const float*)d_in[4];
    const float* g1 = (const float*)d_in[5];
    const float* b1 = (const float*)d_in[6];
    const float* m1 = (const float*)d_in[7];
    const float* v1 = (const float*)d_in[8];
    const float* W2 = (const float*)d_in[9];
    const float* g2 = (const float*)d_in[10];
    const float* b2 = (const float*)d_in[11];
    const float* m2 = (const float*)d_in[12];
    const float* v2 = (const float*)d_in[13];
    float* out = (float*)d_out;

    float* X;  cudaGetSymbolAddress((void**)&X,  g_X);
    float* Y;  cudaGetSymbolAddress((void**)&Y,  g_Y);
    float* Wa; cudaGetSymbolAddress((void**)&Wa, g_W1r);
    float* Wb; cudaGetSymbolAddress((void**)&Wb, g_W2r);

    cudaFuncSetAttribute(gemm_tc, cudaFuncAttributeMaxDynamicSharedMemorySize, SMEMB);

    prep_kernel<<<1024 + 4096 + 16384, 256>>>(W1, W2, known_feats, unknow_feats);
    knn_kernel<<<dim3(NPT/256, B_), 256>>>(unknown, known);
    interp_kernel<<<NTOT/8, 256>>>();

    gemm_tc<<<dim3(NTOT/256, 4), 256, SMEMB>>>(Wa, X, Y,   g1, b1, m1, v1, 0);
    gemm_tc<<<dim3(NTOT/256, 4), 256, SMEMB>>>(Wb, Y, out, g2, b2, m2, v2, 1);

    (void)in_sizes; (void)n_in; (void)out_size;
}

// round 6
// speedup vs baseline: 1.0814x; 1.0814x over previous
#include <cuda_runtime.h>
#include <cstdint>
#include <math.h>

#define B_    8
#define NPT   8192
#define MPT   2048
#define C_    256
#define H_    512
#define NTOT  (B_*NPT)

// ---------------- scratch ----------------
__device__ float g_X[(size_t)NTOT * H_];          // [p][perm8(k)] layer-1 input (tf32)
__device__ float g_Y[(size_t)NTOT * H_];          // [p][perm8(o)] layer-1 output (tf32)
__device__ float g_kft[(size_t)B_ * MPT * C_];    // known_feats transposed [b][m][c]
__device__ float g_W1r[H_ * H_];                  // tf32, k-permuted cols
__device__ float g_W2r[H_ * H_];
__device__ int   g_idx[NTOT * 3];
__device__ float g_w[NTOT * 3];

__device__ __forceinline__ float tf32r(float x) {
    asm("cvt.rna.tf32.f32 %0, %1;" : "=f"(x) : "f"(x));
    return x;
}
// k-permutation within each 8-group: [k0,k4,k1,k5,k2,k6,k3,k7]
__device__ __forceinline__ int perm8(int k) {
    return (k & ~7) | ((k & 3) << 1) | ((k >> 2) & 1);
}
__device__ __forceinline__ void cp16(void* s, const void* g) {
    uint32_t a;
    asm("{ .reg .u64 t; cvta.to.shared.u64 t, %1; cvt.u32.u64 %0, t; }" : "=r"(a) : "l"(s));
    asm volatile("cp.async.cg.shared.global [%0], [%1], 16;\n" :: "r"(a), "l"(g));
}

// ---------------- fused prep: round_w (1024 blks) + tr_kf (4096) + tr_uf (16384) ----------------
__global__ __launch_bounds__(256)
void prep_kernel(const float* __restrict__ W1, const float* __restrict__ W2,
                 const float* __restrict__ kf, const float* __restrict__ uf)
{
    __shared__ float t[32][33];
    const int bid = blockIdx.x;
    const int tid = threadIdx.x;

    if (bid < 1024) {
        int i = bid * 256 + tid;
        int o = i >> 9, k = i & 511;
        g_W1r[o * H_ + perm8(k)] = tf32r(W1[i]);
        g_W2r[o * H_ + perm8(k)] = tf32r(W2[i]);
        return;
    }
    const int x = tid & 31, y0 = tid >> 5;
    if (bid < 1024 + 4096) {
        const int idx = bid - 1024;
        const int m0 = (idx & 63) * 32;
        const int c0 = ((idx >> 6) & 7) * 32;
        const int b  = idx >> 9;
        #pragma unroll
        for (int yy = 0; yy < 32; yy += 8)
            t[y0+yy][x] = kf[((size_t)b*C_ + c0+y0+yy)*MPT + m0 + x];
        __syncthreads();
        #pragma unroll
        for (int yy = 0; yy < 32; yy += 8)
            g_kft[((size_t)b*MPT + m0 + y0+yy)*C_ + c0 + x] = t[x][y0+yy];
    } else {
        const int idx = bid - 1024 - 4096;
        const int j0 = (idx & 255) * 32;
        const int c0 = ((idx >> 8) & 7) * 32;
        const int b  = idx >> 11;
        #pragma unroll
        for (int yy = 0; yy < 32; yy += 8)
            t[y0+yy][x] = uf[((size_t)b*C_ + c0+y0+yy)*NPT + j0 + x];
        __syncthreads();
        #pragma unroll
        for (int yy = 0; yy < 32; yy += 8)
            g_X[((size_t)b*NPT + j0 + y0+yy)*H_ + C_ + perm8(c0 + x)] = tf32r(t[x][y0+yy]);
    }
}

// ---------------- 3-NN + weights ----------------
__global__ __launch_bounds__(256)
void knn_kernel(const float* __restrict__ unknown, const float* __restrict__ known)
{
    __shared__ float kx[MPT], ky[MPT], kz[MPT];
    const int b = blockIdx.y;
    const float* kb = known + (size_t)b * MPT * 3;
    for (int i = threadIdx.x; i < MPT; i += 256) {
        kx[i] = kb[i*3+0]; ky[i] = kb[i*3+1]; kz[i] = kb[i*3+2];
    }
    __syncthreads();

    const int q = blockIdx.x * 256 + threadIdx.x;
    const float* up = unknown + ((size_t)b * NPT + q) * 3;
    const float ux = up[0], uy = up[1], uz = up[2];

    float d0 = 1e30f, d1 = 1e30f, d2 = 1e30f;
    int   i0 = 0,     i1 = 0,     i2 = 0;
    #pragma unroll 4
    for (int i = 0; i < MPT; i++) {
        float dx = kx[i]-ux, dy = ky[i]-uy, dz = kz[i]-uz;
        float d = dx*dx + dy*dy + dz*dz;
        if (d < d2) {
            if (d < d1) {
                if (d < d0) { d2=d1; i2=i1; d1=d0; i1=i0; d0=d; i0=i; }
                else        { d2=d1; i2=i1; d1=d;  i1=i; }
            } else          { d2=d;  i2=i; }
        }
    }
    const float r0 = 1.f/(d0+1e-8f), r1 = 1.f/(d1+1e-8f), r2 = 1.f/(d2+1e-8f);
    const float s = 1.f/(r0+r1+r2);
    const int gi = b * NPT + q;
    g_idx[gi*3+0] = i0; g_idx[gi*3+1] = i1; g_idx[gi*3+2] = i2;
    g_w[gi*3+0] = r0*s; g_w[gi*3+1] = r1*s; g_w[gi*3+2] = r2*s;
}

// ---------------- interpolate -> X[p][perm8(0..255)] (tf32); warp per point ----------------
__global__ __launch_bounds__(256)
void interp_kernel()
{
    const int p = blockIdx.x * 8 + (threadIdx.x >> 5);
    const int lane = threadIdx.x & 31;
    const int b = p >> 13;

    const int   i0 = g_idx[p*3+0], i1 = g_idx[p*3+1], i2 = g_idx[p*3+2];
    const float w0 = g_w[p*3+0],   w1 = g_w[p*3+1],   w2 = g_w[p*3+2];

    const float* r0 = g_kft + ((size_t)b*MPT + i0)*C_ + lane*8;
    const float* r1 = g_kft + ((size_t)b*MPT + i1)*C_ + lane*8;
    const float* r2 = g_kft + ((size_t)b*MPT + i2)*C_ + lane*8;

    float4 a0 = *(const float4*)r0, a1 = *(const float4*)(r0+4);
    float4 c0 = *(const float4*)r1, c1 = *(const float4*)(r1+4);
    float4 e0 = *(const float4*)r2, e1 = *(const float4*)(r2+4);

    float lo[4], hi[4];
    lo[0] = tf32r(w0*a0.x + w1*c0.x + w2*e0.x);
    lo[1] = tf32r(w0*a0.y + w1*c0.y + w2*e0.y);
    lo[2] = tf32r(w0*a0.z + w1*c0.z + w2*e0.z);
    lo[3] = tf32r(w0*a0.w + w1*c0.w + w2*e0.w);
    hi[0] = tf32r(w0*a1.x + w1*c1.x + w2*e1.x);
    hi[1] = tf32r(w0*a1.y + w1*c1.y + w2*e1.y);
    hi[2] = tf32r(w0*a1.z + w1*c1.z + w2*e1.z);
    hi[3] = tf32r(w0*a1.w + w1*c1.w + w2*e1.w);

    // perm8 within the 8-group: [lo0,hi0,lo1,hi1 | lo2,hi2,lo3,hi3]
    float4 o0 = make_float4(lo[0], hi[0], lo[1], hi[1]);
    float4 o1 = make_float4(lo[2], hi[2], lo[3], hi[3]);
    float* xp = g_X + (size_t)p*H_ + lane*8;
    *(float4*)xp = o0;
    *(float4*)(xp+4) = o1;
}

// ---------------- tf32 mma.sync GEMM: BM=128, BN=256, BK=32, 512 thr, warp 64x32 ----------------
#define LDT     40
#define A_F     (128*LDT)                  // 5120
#define B_F     (256*LDT)                  // 10240
#define STAGE_F (A_F + B_F)                // 15360 floats (61440 B)
#define NSTAGE  3
#define SMEMB   (NSTAGE*STAGE_F*4)         // 184320 B

__device__ __forceinline__ void mma_tf32(float* c, const uint32_t* a, const uint32_t* b)
{
    asm volatile(
        "mma.sync.aligned.m16n8k8.row.col.f32.tf32.tf32.f32 "
        "{%0,%1,%2,%3}, {%4,%5,%6,%7}, {%8,%9}, {%0,%1,%2,%3};"
        : "+f"(c[0]), "+f"(c[1]), "+f"(c[2]), "+f"(c[3])
        : "r"(a[0]), "r"(a[1]), "r"(a[2]), "r"(a[3]), "r"(b[0]), "r"(b[1]));
}

__device__ __forceinline__ void load_stage(const float* __restrict__ A, const float* __restrict__ Xn,
                                           int m0, int n0, int kt, float* st, int tid)
{
    const int k0 = kt * 32;
    float* sA = st;
    float* sB = st + A_F;
    #pragma unroll
    for (int i = 0; i < 2; i++) {
        int idx = tid + i*512;             // 0..1023
        int row = idx >> 3;
        int c   = idx & 7;
        cp16(sA + row*LDT + c*4, A + (size_t)(m0 + row)*H_ + k0 + c*4);
    }
    #pragma unroll
    for (int i = 0; i < 4; i++) {
        int idx = tid + i*512;             // 0..2047
        int row = idx >> 3;
        int c   = idx & 7;
        cp16(sB + row*LDT + c*4, Xn + (size_t)(n0 + row)*H_ + k0 + c*4);
    }
    asm volatile("cp.async.commit_group;\n");
}

__global__ __launch_bounds__(512, 1)
void gemm_tc(const float* __restrict__ A, const float* __restrict__ Xn, float* __restrict__ Out,
             const float* __restrict__ G, const float* __restrict__ Bb,
             const float* __restrict__ Mu, const float* __restrict__ Va, int mode)
{
    extern __shared__ float sm[];
    const int tid  = threadIdx.x;
    const int wid  = tid >> 5;             // 0..15
    const int lane = tid & 31;
    const int g    = lane >> 2;
    const int ctib = lane & 3;
    const int wm0  = (wid >> 3) * 64;      // 0 or 64
    const int wn0  = (wid & 7)  * 32;      // 0..224
    const int n0   = blockIdx.x * 256;
    const int m0   = blockIdx.y * 128;

    float acc[4][4][4];
    #pragma unroll
    for (int mt = 0; mt < 4; mt++)
        #pragma unroll
        for (int nt = 0; nt < 4; nt++)
            #pragma unroll
            for (int q = 0; q < 4; q++) acc[mt][nt][q] = 0.0f;

    load_stage(A, Xn, m0, n0, 0, sm, tid);
    load_stage(A, Xn, m0, n0, 1, sm + STAGE_F, tid);

    for (int kt = 0; kt < 16; kt++) {
        if (kt < 15) asm volatile("cp.async.wait_group 1;\n");
        else         asm volatile("cp.async.wait_group 0;\n");
        __syncthreads();

        // refill stage (kt+2)%3 — last read at iter kt-1, free after this sync
        if (kt + 2 < 16)
            load_stage(A, Xn, m0, n0, kt + 2, sm + ((kt + 2) % NSTAGE) * STAGE_F, tid);

        const float* sA = sm + (kt % NSTAGE) * STAGE_F;
        const float* sB = sA + A_F;

        #pragma unroll
        for (int kk = 0; kk < 4; kk++) {
            const int kb = kk * 8;
            uint32_t af[4][4], bf[4][2];
            #pragma unroll
            for (int mt = 0; mt < 4; mt++) {
                const float* pa = sA + (wm0 + mt*16 + g)*LDT + kb + 2*ctib;
                float2 lo = *(const float2*)pa;
                float2 hi = *(const float2*)(pa + 8*LDT);
                af[mt][0] = __float_as_uint(lo.x);
                af[mt][1] = __float_as_uint(hi.x);
                af[mt][2] = __float_as_uint(lo.y);
                af[mt][3] = __float_as_uint(hi.y);
            }
            #pragma unroll
            for (int nt = 0; nt < 4; nt++) {
                float2 bb = *(const float2*)(sB + (wn0 + nt*8 + g)*LDT + kb + 2*ctib);
                bf[nt][0] = __float_as_uint(bb.x);
                bf[nt][1] = __float_as_uint(bb.y);
            }
            #pragma unroll
            for (int mt = 0; mt < 4; mt++)
                #pragma unroll
                for (int nt = 0; nt < 4; nt++)
                    mma_tf32(acc[mt][nt], af[mt], bf[nt]);
        }
        __syncthreads();
    }

    // -------- epilogue: BN + ReLU, staged through smem --------
    float* patch = sm + wid * 2304;

    if (mode == 0) {
        // patch [n][m] 32x64 stride 68; m positions perm8-permuted (Y feeds layer-2 as k)
        #pragma unroll
        for (int mt = 0; mt < 4; mt++) {
            const int o0 = m0 + wm0 + mt*16 + g;
            const float sc0 = G[o0]   * rsqrtf(Va[o0]   + 1e-5f);
            const float sh0 = Bb[o0]   - Mu[o0]  * sc0;
            const float sc1 = G[o0+8] * rsqrtf(Va[o0+8] + 1e-5f);
            const float sh1 = Bb[o0+8] - Mu[o0+8] * sc1;
            const int ml  = perm8(mt*16 + g);
            const int mlh = perm8(mt*16 + g + 8);
            #pragma unroll
            for (int nt = 0; nt < 4; nt++) {
                const int nl = nt*8 + 2*ctib;
                patch[ nl   *68 + ml ] = tf32r(fmaxf(fmaf(acc[mt][nt][0], sc0, sh0), 0.f));
                patch[(nl+1)*68 + ml ] = tf32r(fmaxf(fmaf(acc[mt][nt][1], sc0, sh0), 0.f));
                patch[ nl   *68 + mlh] = tf32r(fmaxf(fmaf(acc[mt][nt][2], sc1, sh1), 0.f));
                patch[(nl+1)*68 + mlh] = tf32r(fmaxf(fmaf(acc[mt][nt][3], sc1, sh1), 0.f));
            }
        }
        __syncwarp();
        float* yb = Out + (size_t)(n0 + wn0) * H_ + m0 + wm0;
        #pragma unroll
        for (int r = 0; r < 32; r++)
            *(float2*)(yb + (size_t)r * H_ + lane*2) = *(float2*)(patch + r*68 + lane*2);
    } else {
        // patch [m][n] 64x32 stride 36, physical layout
        #pragma unroll
        for (int mt = 0; mt < 4; mt++) {
            const int o0 = m0 + wm0 + mt*16 + g;
            const float sc0 = G[o0]   * rsqrtf(Va[o0]   + 1e-5f);
            const float sh0 = Bb[o0]   - Mu[o0]  * sc0;
            const float sc1 = G[o0+8] * rsqrtf(Va[o0+8] + 1e-5f);
            const float sh1 = Bb[o0+8] - Mu[o0+8] * sc1;
            const int ml = mt*16 + g;
            #pragma unroll
            for (int nt = 0; nt < 4; nt++) {
                const int nl = nt*8 + 2*ctib;
                patch[ ml   *36 + nl  ] = fmaxf(fmaf(acc[mt][nt][0], sc0, sh0), 0.f);
                patch[ ml   *36 + nl+1] = fmaxf(fmaf(acc[mt][nt][1], sc0, sh0), 0.f);
                patch[(ml+8)*36 + nl  ] = fmaxf(fmaf(acc[mt][nt][2], sc1, sh1), 0.f);
                patch[(ml+8)*36 + nl+1] = fmaxf(fmaf(acc[mt][nt][3], sc1, sh1), 0.f);
            }
        }
        __syncwarp();
        const int b  = n0 >> 13;
        const int j0 = (n0 & (NPT-1)) + wn0;
        float* ob = Out + ((size_t)b * H_ + m0 + wm0) * NPT + j0;
        #pragma unroll
        for (int r = 0; r < 64; r++)
            ob[(size_t)r * NPT + lane] = patch[r*36 + lane];
    }
}

// ---------------- launch ----------------
extern "C" void kernel_launch(void* const* d_in, const int* in_sizes, int n_in,
                              void* d_out, int out_size)
{
    const float* unknown      = (const float*)d_in[0];
    const float* known        = (const float*)d_in[1];
    const float* unknow_feats = (const float*)d_in[2];
    const float* known_feats  = (const float*)d_in[3];
    const float* W1 = (const float*)d_in[4];
    const float* g1 = (const float*)d_in[5];
    const float* b1 = (const float*)d_in[6];
    const float* m1 = (const float*)d_in[7];
    const float* v1 = (const float*)d_in[8];
    const float* W2 = (const float*)d_in[9];
    const float* g2 = (const float*)d_in[10];
    const float* b2 = (const float*)d_in[11];
    const float* m2 = (const float*)d_in[12];
    const float* v2 = (const float*)d_in[13];
    float* out = (float*)d_out;

    float* X;  cudaGetSymbolAddress((void**)&X,  g_X);
    float* Y;  cudaGetSymbolAddress((void**)&Y,  g_Y);
    float* Wa; cudaGetSymbolAddress((void**)&Wa, g_W1r);
    float* Wb; cudaGetSymbolAddress((void**)&Wb, g_W2r);

    cudaFuncSetAttribute(gemm_tc, cudaFuncAttributeMaxDynamicSharedMemorySize, SMEMB);

    prep_kernel<<<1024 + 4096 + 16384, 256>>>(W1, W2, known_feats, unknow_feats);
    knn_kernel<<<dim3(NPT/256, B_), 256>>>(unknown, known);
    interp_kernel<<<NTOT/8, 256>>>();

    gemm_tc<<<dim3(NTOT/256, 4), 512, SMEMB>>>(Wa, X, Y,   g1, b1, m1, v1, 0);
    gemm_tc<<<dim3(NTOT/256, 4), 512, SMEMB>>>(Wb, Y, out, g2, b2, m2, v2, 1);

    (void)in_sizes; (void)n_in; (void)out_size;
}

// round 7
// speedup vs baseline: 1.2072x; 1.1164x over previous
#include <cuda_runtime.h>
#include <cstdint>
#include <math.h>

#define B_    8
#define NPT   8192
#define MPT   2048
#define C_    256
#define H_    512
#define NTOT  (B_*NPT)

#define LDT     40                          // padded row stride (floats)
#define A_ROWF  (128*LDT)                   // 5120 floats  (A tile per ktile)
#define B_ROWF  (256*LDT)                   // 10240 floats (B tile per ktile)
#define STAGE_F (A_ROWF + B_ROWF)           // 15360 floats = 61440 B
#define NSTAGE  3
#define SM_HDR  32                          // 128 B header for mbarriers
#define SMEMBT  ((SM_HDR + NSTAGE*STAGE_F)*4)

// ---------------- scratch: tiled, padded operand layouts ----------------
// X/Y tiled: [nblk 256][ktile 16][row 256][LDT 40]
__device__ float g_Xt[(size_t)256 * 16 * B_ROWF];
__device__ float g_Yt[(size_t)256 * 16 * B_ROWF];
// W tiled:   [mblk 4][ktile 16][row 128][LDT 40]
__device__ float g_W1t[4 * 16 * A_ROWF];
__device__ float g_W2t[4 * 16 * A_ROWF];
__device__ float g_kft[(size_t)B_ * MPT * C_];
__device__ int   g_idx[NTOT * 3];
__device__ float g_w[NTOT * 3];

__device__ __forceinline__ float tf32r(float x) {
    asm("cvt.rna.tf32.f32 %0, %1;" : "=f"(x) : "f"(x));
    return x;
}
__device__ __forceinline__ int perm8(int k) {
    return (k & ~7) | ((k & 3) << 1) | ((k >> 2) & 1);
}
__device__ __forceinline__ uint32_t smem_u32(const void* p) {
    uint32_t a;
    asm("{ .reg .u64 t; cvta.to.shared.u64 t, %1; cvt.u32.u64 %0, t; }" : "=r"(a) : "l"(p));
    return a;
}
__device__ __forceinline__ void bulk_cp(uint32_t dst, const void* src, uint32_t bytes, uint32_t mbar) {
    asm volatile("cp.async.bulk.shared::cta.global.mbarrier::complete_tx::bytes [%0], [%1], %2, [%3];"
                 :: "r"(dst), "l"(src), "r"(bytes), "r"(mbar) : "memory");
}
__device__ __forceinline__ void mbar_init(uint32_t a, uint32_t cnt) {
    asm volatile("mbarrier.init.shared.b64 [%0], %1;" :: "r"(a), "r"(cnt) : "memory");
}
__device__ __forceinline__ void mbar_expect(uint32_t a, uint32_t bytes) {
    asm volatile("mbarrier.arrive.expect_tx.shared.b64 _, [%0], %1;" :: "r"(a), "r"(bytes) : "memory");
}
__device__ __forceinline__ void mbar_wait(uint32_t a, uint32_t ph) {
    asm volatile("{\n\t.reg .pred P;\n\tWL%=:\n\t"
                 "mbarrier.try_wait.parity.acquire.cta.shared::cta.b64 P, [%0], %1, 0x989680;\n\t"
                 "@!P bra WL%=;\n\t}" :: "r"(a), "r"(ph) : "memory");
}

// ---------------- fused prep: weights->tiled tf32 + tr_kf + tr_uf->X_tiled ----------------
__global__ __launch_bounds__(256)
void prep_kernel(const float* __restrict__ W1, const float* __restrict__ W2,
                 const float* __restrict__ kf, const float* __restrict__ uf)
{
    __shared__ float t[32][33];
    const int bid = blockIdx.x;
    const int tid = threadIdx.x;

    if (bid < 1024) {
        int i = bid * 256 + tid;
        int o = i >> 9, k = i & 511;
        size_t a = (size_t)((o >> 7) * 16 + (k >> 5)) * A_ROWF + (o & 127) * LDT + (perm8(k) & 31);
        g_W1t[a] = tf32r(W1[i]);
        g_W2t[a] = tf32r(W2[i]);
        return;
    }
    const int x = tid & 31, y0 = tid >> 5;
    if (bid < 1024 + 4096) {
        const int idx = bid - 1024;
        const int m0 = (idx & 63) * 32;
        const int c0 = ((idx >> 6) & 7) * 32;
        const int b  = idx >> 9;
        #pragma unroll
        for (int yy = 0; yy < 32; yy += 8)
            t[y0+yy][x] = kf[((size_t)b*C_ + c0+y0+yy)*MPT + m0 + x];
        __syncthreads();
        #pragma unroll
        for (int yy = 0; yy < 32; yy += 8)
            g_kft[((size_t)b*MPT + m0 + y0+yy)*C_ + c0 + x] = t[x][y0+yy];
    } else {
        const int idx = bid - 1024 - 4096;
        const int j0 = (idx & 255) * 32;
        const int c0 = ((idx >> 8) & 7) * 32;
        const int b  = idx >> 11;
        #pragma unroll
        for (int yy = 0; yy < 32; yy += 8)
            t[y0+yy][x] = uf[((size_t)b*C_ + c0+y0+yy)*NPT + j0 + x];
        __syncthreads();
        const int ch = C_ + c0 + x;                 // channel -> k position
        const int kt = ch >> 5;
        const int sl = perm8(ch) & 31;
        #pragma unroll
        for (int yy = 0; yy < 32; yy += 8) {
            const int p = b * NPT + j0 + y0 + yy;
            g_Xt[(size_t)((p >> 8) * 16 + kt) * B_ROWF + (p & 255) * LDT + sl] = tf32r(t[x][y0+yy]);
        }
    }
}

// ---------------- 3-NN + weights ----------------
__global__ __launch_bounds__(256)
void knn_kernel(const float* __restrict__ unknown, const float* __restrict__ known)
{
    __shared__ float kx[MPT], ky[MPT], kz[MPT];
    const int b = blockIdx.y;
    const float* kb = known + (size_t)b * MPT * 3;
    for (int i = threadIdx.x; i < MPT; i += 256) {
        kx[i] = kb[i*3+0]; ky[i] = kb[i*3+1]; kz[i] = kb[i*3+2];
    }
    __syncthreads();

    const int q = blockIdx.x * 256 + threadIdx.x;
    const float* up = unknown + ((size_t)b * NPT + q) * 3;
    const float ux = up[0], uy = up[1], uz = up[2];

    float d0 = 1e30f, d1 = 1e30f, d2 = 1e30f;
    int   i0 = 0,     i1 = 0,     i2 = 0;
    #pragma unroll 4
    for (int i = 0; i < MPT; i++) {
        float dx = kx[i]-ux, dy = ky[i]-uy, dz = kz[i]-uz;
        float d = dx*dx + dy*dy + dz*dz;
        if (d < d2) {
            if (d < d1) {
                if (d < d0) { d2=d1; i2=i1; d1=d0; i1=i0; d0=d; i0=i; }
                else        { d2=d1; i2=i1; d1=d;  i1=i; }
            } else          { d2=d;  i2=i; }
        }
    }
    const float r0 = 1.f/(d0+1e-8f), r1 = 1.f/(d1+1e-8f), r2 = 1.f/(d2+1e-8f);
    const float s = 1.f/(r0+r1+r2);
    const int gi = b * NPT + q;
    g_idx[gi*3+0] = i0; g_idx[gi*3+1] = i1; g_idx[gi*3+2] = i2;
    g_w[gi*3+0] = r0*s; g_w[gi*3+1] = r1*s; g_w[gi*3+2] = r2*s;
}

// ---------------- interpolate -> X_tiled ktiles 0..7 (tf32); warp per point ----------------
__global__ __launch_bounds__(256)
void interp_kernel()
{
    const int p = blockIdx.x * 8 + (threadIdx.x >> 5);
    const int lane = threadIdx.x & 31;
    const int b = p >> 13;

    const int   i0 = g_idx[p*3+0], i1 = g_idx[p*3+1], i2 = g_idx[p*3+2];
    const float w0 = g_w[p*3+0],   w1 = g_w[p*3+1],   w2 = g_w[p*3+2];

    const float* r0 = g_kft + ((size_t)b*MPT + i0)*C_ + lane*8;
    const float* r1 = g_kft + ((size_t)b*MPT + i1)*C_ + lane*8;
    const float* r2 = g_kft + ((size_t)b*MPT + i2)*C_ + lane*8;

    float4 a0 = *(const float4*)r0, a1 = *(const float4*)(r0+4);
    float4 c0 = *(const float4*)r1, c1 = *(const float4*)(r1+4);
    float4 e0 = *(const float4*)r2, e1 = *(const float4*)(r2+4);

    float lo[4], hi[4];
    lo[0] = tf32r(w0*a0.x + w1*c0.x + w2*e0.x);
    lo[1] = tf32r(w0*a0.y + w1*c0.y + w2*e0.y);
    lo[2] = tf32r(w0*a0.z + w1*c0.z + w2*e0.z);
    lo[3] = tf32r(w0*a0.w + w1*c0.w + w2*e0.w);
    hi[0] = tf32r(w0*a1.x + w1*c1.x + w2*e1.x);
    hi[1] = tf32r(w0*a1.y + w1*c1.y + w2*e1.y);
    hi[2] = tf32r(w0*a1.z + w1*c1.z + w2*e1.z);
    hi[3] = tf32r(w0*a1.w + w1*c1.w + w2*e1.w);

    // channels lane*8..+7; perm8 order [lo0,hi0,lo1,hi1 | lo2,hi2,lo3,hi3]
    float4 o0 = make_float4(lo[0], hi[0], lo[1], hi[1]);
    float4 o1 = make_float4(lo[2], hi[2], lo[3], hi[3]);
    float* xp = g_Xt + (size_t)((p >> 8) * 16 + (lane >> 2)) * B_ROWF
              + (p & 255) * LDT + (lane & 3) * 8;
    *(float4*)xp = o0;
    *(float4*)(xp+4) = o1;
}

// ---------------- tf32 mma.sync GEMM, TMA-bulk staged ----------------
// A = Wt [mblk][kt][128][40]; B = Bt [nblk][kt][256][40]
__device__ __forceinline__ void mma_tf32(float* c, const uint32_t* a, const uint32_t* b)
{
    asm volatile(
        "mma.sync.aligned.m16n8k8.row.col.f32.tf32.tf32.f32 "
        "{%0,%1,%2,%3}, {%4,%5,%6,%7}, {%8,%9}, {%0,%1,%2,%3};"
        : "+f"(c[0]), "+f"(c[1]), "+f"(c[2]), "+f"(c[3])
        : "r"(a[0]), "r"(a[1]), "r"(a[2]), "r"(a[3]), "r"(b[0]), "r"(b[1]));
}

__global__ __launch_bounds__(512, 1)
void gemm_tc(const float* __restrict__ Wt, const float* __restrict__ Bt, float* __restrict__ Out,
             const float* __restrict__ G, const float* __restrict__ Bb,
             const float* __restrict__ Mu, const float* __restrict__ Va, int mode)
{
    extern __shared__ float sm[];
    const uint32_t sbase = smem_u32(sm);
    const int tid  = threadIdx.x;
    const int wid  = tid >> 5;
    const int lane = tid & 31;
    const int g    = lane >> 2;
    const int ctib = lane & 3;
    const int wm0  = (wid >> 3) * 64;
    const int wn0  = (wid & 7)  * 32;
    const int mblk = blockIdx.x;           // 0..3  (fastest -> L2 shares B tile)
    const int nblk = blockIdx.y;           // 0..255
    const int m0   = mblk * 128;
    const int n0   = nblk * 256;

    if (tid == 0) {
        mbar_init(sbase + 0, 1);
        mbar_init(sbase + 8, 1);
        mbar_init(sbase + 16, 1);
    }
    __syncthreads();

    const float* Asrc = Wt + (size_t)mblk * 16 * A_ROWF;
    const float* Bsrc = Bt + (size_t)nblk * 16 * B_ROWF;

    if (tid == 0) {
        #pragma unroll
        for (int s = 0; s < 2; s++) {
            uint32_t mb = sbase + s*8;
            uint32_t st = sbase + (SM_HDR + s*STAGE_F)*4;
            mbar_expect(mb, STAGE_F*4);
            bulk_cp(st,              Asrc + (size_t)s*A_ROWF, A_ROWF*4, mb);
            bulk_cp(st + A_ROWF*4,   Bsrc + (size_t)s*B_ROWF, B_ROWF*4, mb);
        }
    }

    float acc[4][4][4];
    #pragma unroll
    for (int mt = 0; mt < 4; mt++)
        #pragma unroll
        for (int nt = 0; nt < 4; nt++)
            #pragma unroll
            for (int q = 0; q < 4; q++) acc[mt][nt][q] = 0.0f;

    for (int kt = 0; kt < 16; kt++) {
        const int s = kt % NSTAGE;
        __syncthreads();                   // stage (kt-1)%3 fully consumed by all warps
        if (tid == 0 && kt + 2 < 16) {
            const int s2 = (kt + 2) % NSTAGE;
            uint32_t mb = sbase + s2*8;
            uint32_t st = sbase + (SM_HDR + s2*STAGE_F)*4;
            mbar_expect(mb, STAGE_F*4);
            bulk_cp(st,            Asrc + (size_t)(kt+2)*A_ROWF, A_ROWF*4, mb);
            bulk_cp(st + A_ROWF*4, Bsrc + (size_t)(kt+2)*B_ROWF, B_ROWF*4, mb);
        }
        mbar_wait(sbase + s*8, (kt / NSTAGE) & 1);

        const float* sA = sm + SM_HDR + s*STAGE_F;
        const float* sB = sA + A_ROWF;

        #pragma unroll
        for (int kk = 0; kk < 4; kk++) {
            const int kb = kk * 8;
            uint32_t af[4][4], bf[4][2];
            #pragma unroll
            for (int mt = 0; mt < 4; mt++) {
                const float* pa = sA + (wm0 + mt*16 + g)*LDT + kb + 2*ctib;
                float2 lo = *(const float2*)pa;
                float2 hi = *(const float2*)(pa + 8*LDT);
                af[mt][0] = __float_as_uint(lo.x);
                af[mt][1] = __float_as_uint(hi.x);
                af[mt][2] = __float_as_uint(lo.y);
                af[mt][3] = __float_as_uint(hi.y);
            }
            #pragma unroll
            for (int nt = 0; nt < 4; nt++) {
                float2 bb = *(const float2*)(sB + (wn0 + nt*8 + g)*LDT + kb + 2*ctib);
                bf[nt][0] = __float_as_uint(bb.x);
                bf[nt][1] = __float_as_uint(bb.y);
            }
            #pragma unroll
            for (int mt = 0; mt < 4; mt++)
                #pragma unroll
                for (int nt = 0; nt < 4; nt++)
                    mma_tf32(acc[mt][nt], af[mt], bf[nt]);
        }
    }
    __syncthreads();

    // -------- epilogue: BN + ReLU, staged through smem --------
    float* patch = sm + SM_HDR + wid * 2304;

    if (mode == 0) {
        // write Y_tiled; m (=layer-2 k) positions perm8'd, tiled addressing
        #pragma unroll
        for (int mt = 0; mt < 4; mt++) {
            const int o0 = m0 + wm0 + mt*16 + g;
            const float sc0 = G[o0]   * rsqrtf(Va[o0]   + 1e-5f);
            const float sh0 = Bb[o0]   - Mu[o0]  * sc0;
            const float sc1 = G[o0+8] * rsqrtf(Va[o0+8] + 1e-5f);
            const float sh1 = Bb[o0+8] - Mu[o0+8] * sc1;
            const int ml  = perm8(mt*16 + g);
            const int mlh = perm8(mt*16 + g + 8);
            #pragma unroll
            for (int nt = 0; nt < 4; nt++) {
                const int nl = nt*8 + 2*ctib;
                patch[ nl   *68 + ml ] = tf32r(fmaxf(fmaf(acc[mt][nt][0], sc0, sh0), 0.f));
                patch[(nl+1)*68 + ml ] = tf32r(fmaxf(fmaf(acc[mt][nt][1], sc0, sh0), 0.f));
                patch[ nl   *68 + mlh] = tf32r(fmaxf(fmaf(acc[mt][nt][2], sc1, sh1), 0.f));
                patch[(nl+1)*68 + mlh] = tf32r(fmaxf(fmaf(acc[mt][nt][3], sc1, sh1), 0.f));
            }
        }
        __syncwarp();
        // cols m0+wm0 .. +64 span ktiles kt0, kt0+1 (lanes 0-15 / 16-31)
        const int kt0 = (m0 + wm0) >> 5;
        const int ktw = kt0 + (lane >> 4);
        float* yb = Out + (size_t)(nblk * 16 + ktw) * B_ROWF + (wn0) * LDT + ((lane*2) & 31);
        #pragma unroll
        for (int r = 0; r < 32; r++)
            *(float2*)(yb + r * LDT) = *(float2*)(patch + r*68 + lane*2);
    } else {
        // write d_out (B,512,8192) physical
        #pragma unroll
        for (int mt = 0; mt < 4; mt++) {
            const int o0 = m0 + wm0 + mt*16 + g;
            const float sc0 = G[o0]   * rsqrtf(Va[o0]   + 1e-5f);
            const float sh0 = Bb[o0]   - Mu[o0]  * sc0;
            const float sc1 = G[o0+8] * rsqrtf(Va[o0+8] + 1e-5f);
            const float sh1 = Bb[o0+8] - Mu[o0+8] * sc1;
            const int ml = mt*16 + g;
            #pragma unroll
            for (int nt = 0; nt < 4; nt++) {
                const int nl = nt*8 + 2*ctib;
                patch[ ml   *36 + nl  ] = fmaxf(fmaf(acc[mt][nt][0], sc0, sh0), 0.f);
                patch[ ml   *36 + nl+1] = fmaxf(fmaf(acc[mt][nt][1], sc0, sh0), 0.f);
                patch[(ml+8)*36 + nl  ] = fmaxf(fmaf(acc[mt][nt][2], sc1, sh1), 0.f);
                patch[(ml+8)*36 + nl+1] = fmaxf(fmaf(acc[mt][nt][3], sc1, sh1), 0.f);
            }
        }
        __syncwarp();
        const int b  = n0 >> 13;
        const int j0 = (n0 & (NPT-1)) + wn0;
        float* ob = Out + ((size_t)b * H_ + m0 + wm0) * NPT + j0;
        #pragma unroll
        for (int r = 0; r < 64; r++)
            ob[(size_t)r * NPT + lane] = patch[r*36 + lane];
    }
}

// ---------------- launch ----------------
extern "C" void kernel_launch(void* const* d_in, const int* in_sizes, int n_in,
                              void* d_out, int out_size)
{
    const float* unknown      = (const float*)d_in[0];
    const float* known        = (const float*)d_in[1];
    const float* unknow_feats = (const float*)d_in[2];
    const float* known_feats  = (const float*)d_in[3];
    const float* W1 = (const float*)d_in[4];
    const float* g1 = (const float*)d_in[5];
    const float* b1 = (const float*)d_in[6];
    const float* m1 = (const float*)d_in[7];
    const float* v1 = (const float*)d_in[8];
    const float* W2 = (const float*)d_in[9];
    const float* g2 = (const float*)d_in[10];
    const float* b2 = (const float*)d_in[11];
    const float* m2 = (const float*)d_in[12];
    const float* v2 = (const float*)d_in[13];
    float* out = (float*)d_out;

    float* Xt;  cudaGetSymbolAddress((void**)&Xt,  g_Xt);
    float* Yt;  cudaGetSymbolAddress((void**)&Yt,  g_Yt);
    float* W1t; cudaGetSymbolAddress((void**)&W1t, g_W1t);
    float* W2t; cudaGetSymbolAddress((void**)&W2t, g_W2t);

    cudaFuncSetAttribute(gemm_tc, cudaFuncAttributeMaxDynamicSharedMemorySize, SMEMBT);

    prep_kernel<<<1024 + 4096 + 16384, 256>>>(W1, W2, known_feats, unknow_feats);
    knn_kernel<<<dim3(NPT/256, B_), 256>>>(unknown, known);
    interp_kernel<<<NTOT/8, 256>>>();

    gemm_tc<<<dim3(4, 256), 512, SMEMBT>>>(W1t, Xt, Yt,  g1, b1, m1, v1, 0);
    gemm_tc<<<dim3(4, 256), 512, SMEMBT>>>(W2t, Yt, out, g2, b2, m2, v2, 1);

    (void)in_sizes; (void)n_in; (void)out_size;
}

// round 8
// speedup vs baseline: 1.6171x; 1.3395x over previous
#include <cuda_runtime.h>
#include <cuda_fp16.h>
#include <cstdint>
#include <math.h>

#define B_    8
#define NPT   8192
#define MPT   2048
#define C_    256
#define H_    512
#define NTOT  (B_*NPT)

#define LDTH    80                          // padded row stride (halves) per K64 ktile
#define A_ROWH  (128*LDTH)                  // 10240 halves = 20480 B
#define B_ROWH  (256*LDTH)                  // 20480 halves = 40960 B
#define STAGE_H (A_ROWH + B_ROWH)           // 30720 halves = 61440 B
#define NSTAGE  3
#define SM_HDR_B 128
#define SMEMBT  (SM_HDR_B + NSTAGE*STAGE_H*2)

// ---------------- scratch: tiled fp16 operands ----------------
// X/Y tiled: [nblk 256][ktile 8][row 256][LDTH]
__device__ __half g_Xt[(size_t)256 * 8 * B_ROWH];
__device__ __half g_Yt[(size_t)256 * 8 * B_ROWH];
// W tiled:   [mblk 4][ktile 8][row 128][LDTH]
__device__ __half g_W1t[4 * 8 * A_ROWH];
__device__ __half g_W2t[4 * 8 * A_ROWH];
__device__ float  g_kft[(size_t)B_ * MPT * C_];
__device__ int    g_idx[NTOT * 3];
__device__ float  g_w[NTOT * 3];

// position of k-local l (0..63) within a ktile row: pair-interleaved per 16-group
__device__ __forceinline__ int kpos64(int l) {
    int p  = (l >> 1) & 7;
    int pp = ((p & 3) << 1) | (p >> 2);
    return (l & ~15) | (pp << 1) | (l & 1);
}
__device__ __forceinline__ uint32_t smem_u32(const void* p) {
    uint32_t a;
    asm("{ .reg .u64 t; cvta.to.shared.u64 t, %1; cvt.u32.u64 %0, t; }" : "=r"(a) : "l"(p));
    return a;
}
__device__ __forceinline__ void bulk_cp(uint32_t dst, const void* src, uint32_t bytes, uint32_t mbar) {
    asm volatile("cp.async.bulk.shared::cta.global.mbarrier::complete_tx::bytes [%0], [%1], %2, [%3];"
                 :: "r"(dst), "l"(src), "r"(bytes), "r"(mbar) : "memory");
}
__device__ __forceinline__ void mbar_init(uint32_t a, uint32_t cnt) {
    asm volatile("mbarrier.init.shared.b64 [%0], %1;" :: "r"(a), "r"(cnt) : "memory");
}
__device__ __forceinline__ void mbar_expect(uint32_t a, uint32_t bytes) {
    asm volatile("mbarrier.arrive.expect_tx.shared.b64 _, [%0], %1;" :: "r"(a), "r"(bytes) : "memory");
}
__device__ __forceinline__ void mbar_wait(uint32_t a, uint32_t ph) {
    asm volatile("{\n\t.reg .pred P;\n\tWL%=:\n\t"
                 "mbarrier.try_wait.parity.acquire.cta.shared::cta.b64 P, [%0], %1, 0x989680;\n\t"
                 "@!P bra WL%=;\n\t}" :: "r"(a), "r"(ph) : "memory");
}

// ---------------- fused prep: W->tiled f16 + tr_kf + tr_uf->X_tiled f16 ----------------
__global__ __launch_bounds__(256)
void prep_kernel(const float* __restrict__ W1, const float* __restrict__ W2,
                 const float* __restrict__ kf, const float* __restrict__ uf)
{
    __shared__ float t[32][33];
    const int bid = blockIdx.x;
    const int tid = threadIdx.x;

    if (bid < 1024) {
        int i = bid * 256 + tid;
        int o = i >> 9, k = i & 511;
        size_t a = (size_t)((o >> 7) * 8 + (k >> 6)) * A_ROWH + (o & 127) * LDTH + kpos64(k & 63);
        g_W1t[a] = __float2half_rn(W1[i]);
        g_W2t[a] = __float2half_rn(W2[i]);
        return;
    }
    const int x = tid & 31, y0 = tid >> 5;
    if (bid < 1024 + 4096) {
        const int idx = bid - 1024;
        const int m0 = (idx & 63) * 32;
        const int c0 = ((idx >> 6) & 7) * 32;
        const int b  = idx >> 9;
        #pragma unroll
        for (int yy = 0; yy < 32; yy += 8)
            t[y0+yy][x] = kf[((size_t)b*C_ + c0+y0+yy)*MPT + m0 + x];
        __syncthreads();
        #pragma unroll
        for (int yy = 0; yy < 32; yy += 8)
            g_kft[((size_t)b*MPT + m0 + y0+yy)*C_ + c0 + x] = t[x][y0+yy];
    } else {
        const int idx = bid - 1024 - 4096;
        const int j0 = (idx & 255) * 32;
        const int c0 = ((idx >> 8) & 7) * 32;
        const int b  = idx >> 11;
        #pragma unroll
        for (int yy = 0; yy < 32; yy += 8)
            t[y0+yy][x] = uf[((size_t)b*C_ + c0+y0+yy)*NPT + j0 + x];
        __syncthreads();
        const int ch = C_ + c0 + x;
        const int kt = ch >> 6;
        const int sl = kpos64(ch & 63);
        #pragma unroll
        for (int yy = 0; yy < 32; yy += 8) {
            const int p = b * NPT + j0 + y0 + yy;
            g_Xt[(size_t)((p >> 8) * 8 + kt) * B_ROWH + (p & 255) * LDTH + sl] =
                __float2half_rn(t[x][y0+yy]);
        }
    }
}

// ---------------- 3-NN + weights ----------------
__global__ __launch_bounds__(256)
void knn_kernel(const float* __restrict__ unknown, const float* __restrict__ known)
{
    __shared__ float kx[MPT], ky[MPT], kz[MPT];
    const int b = blockIdx.y;
    const float* kb = known + (size_t)b * MPT * 3;
    for (int i = threadIdx.x; i < MPT; i += 256) {
        kx[i] = kb[i*3+0]; ky[i] = kb[i*3+1]; kz[i] = kb[i*3+2];
    }
    __syncthreads();

    const int q = blockIdx.x * 256 + threadIdx.x;
    const float* up = unknown + ((size_t)b * NPT + q) * 3;
    const float ux = up[0], uy = up[1], uz = up[2];

    float d0 = 1e30f, d1 = 1e30f, d2 = 1e30f;
    int   i0 = 0,     i1 = 0,     i2 = 0;
    #pragma unroll 4
    for (int i = 0; i < MPT; i++) {
        float dx = kx[i]-ux, dy = ky[i]-uy, dz = kz[i]-uz;
        float d = dx*dx + dy*dy + dz*dz;
        if (d < d2) {
            if (d < d1) {
                if (d < d0) { d2=d1; i2=i1; d1=d0; i1=i0; d0=d; i0=i; }
                else        { d2=d1; i2=i1; d1=d;  i1=i; }
            } else          { d2=d;  i2=i; }
        }
    }
    const float r0 = 1.f/(d0+1e-8f), r1 = 1.f/(d1+1e-8f), r2 = 1.f/(d2+1e-8f);
    const float s = 1.f/(r0+r1+r2);
    const int gi = b * NPT + q;
    g_idx[gi*3+0] = i0; g_idx[gi*3+1] = i1; g_idx[gi*3+2] = i2;
    g_w[gi*3+0] = r0*s; g_w[gi*3+1] = r1*s; g_w[gi*3+2] = r2*s;
}

// ---------------- interpolate -> X_tiled f16 (channels 0..255); warp per point ----------------
__global__ __launch_bounds__(256)
void interp_kernel()
{
    const int p = blockIdx.x * 8 + (threadIdx.x >> 5);
    const int lane = threadIdx.x & 31;
    const int b = p >> 13;

    const int   i0 = g_idx[p*3+0], i1 = g_idx[p*3+1], i2 = g_idx[p*3+2];
    const float w0 = g_w[p*3+0],   w1 = g_w[p*3+1],   w2 = g_w[p*3+2];

    const float* r0 = g_kft + ((size_t)b*MPT + i0)*C_ + lane*8;
    const float* r1 = g_kft + ((size_t)b*MPT + i1)*C_ + lane*8;
    const float* r2 = g_kft + ((size_t)b*MPT + i2)*C_ + lane*8;

    float4 a0 = *(const float4*)r0, a1 = *(const float4*)(r0+4);
    float4 c0 = *(const float4*)r1, c1 = *(const float4*)(r1+4);
    float4 e0 = *(const float4*)r2, e1 = *(const float4*)(r2+4);

    float v[8];
    v[0] = w0*a0.x + w1*c0.x + w2*e0.x;
    v[1] = w0*a0.y + w1*c0.y + w2*e0.y;
    v[2] = w0*a0.z + w1*c0.z + w2*e0.z;
    v[3] = w0*a0.w + w1*c0.w + w2*e0.w;
    v[4] = w0*a1.x + w1*c1.x + w2*e1.x;
    v[5] = w0*a1.y + w1*c1.y + w2*e1.y;
    v[6] = w0*a1.z + w1*c1.z + w2*e1.z;
    v[7] = w0*a1.w + w1*c1.w + w2*e1.w;

    // channels ch = lane*8 + t ; ktile = ch>>6 = lane>>3 ; local l = (lane&7)*8 + t
    __half* xp = g_Xt + (size_t)((p >> 8) * 8 + (lane >> 3)) * B_ROWH + (p & 255) * LDTH;
    const int base = (lane & 7) * 8;
    #pragma unroll
    for (int t = 0; t < 8; t++)
        xp[kpos64(base + t)] = __float2half_rn(v[t]);
}

// ---------------- fp16 mma.sync GEMM, bulk-copy staged ----------------
__device__ __forceinline__ void mma_f16(float* c, uint32_t a0, uint32_t a1, uint32_t a2, uint32_t a3,
                                        uint32_t b0, uint32_t b1)
{
    asm volatile(
        "mma.sync.aligned.m16n8k16.row.col.f32.f16.f16.f32 "
        "{%0,%1,%2,%3}, {%4,%5,%6,%7}, {%8,%9}, {%0,%1,%2,%3};"
        : "+f"(c[0]), "+f"(c[1]), "+f"(c[2]), "+f"(c[3])
        : "r"(a0), "r"(a1), "r"(a2), "r"(a3), "r"(b0), "r"(b1));
}

__global__ __launch_bounds__(512, 1)
void gemm_tc(const __half* __restrict__ Wt, const __half* __restrict__ Bt, void* __restrict__ OutV,
             const float* __restrict__ G, const float* __restrict__ Bb,
             const float* __restrict__ Mu, const float* __restrict__ Va, int mode)
{
    extern __shared__ char smraw[];
    __half* smh = (__half*)(smraw + SM_HDR_B);
    const uint32_t sbase = smem_u32(smraw);
    const int tid  = threadIdx.x;
    const int wid  = tid >> 5;
    const int lane = tid & 31;
    const int g    = lane >> 2;
    const int ctib = lane & 3;
    const int wm0  = (wid >> 3) * 64;
    const int wn0  = (wid & 7)  * 32;
    const int mblk = blockIdx.x;           // 0..3 fastest -> L2 shares B tile
    const int nblk = blockIdx.y;           // 0..255
    const int m0   = mblk * 128;
    const int n0   = nblk * 256;

    if (tid == 0) {
        mbar_init(sbase + 0, 1);
        mbar_init(sbase + 8, 1);
        mbar_init(sbase + 16, 1);
    }
    __syncthreads();

    const __half* Asrc = Wt + (size_t)mblk * 8 * A_ROWH;
    const __half* Bsrc = Bt + (size_t)nblk * 8 * B_ROWH;

    if (tid == 0) {
        #pragma unroll
        for (int s = 0; s < 2; s++) {
            uint32_t mb = sbase + s*8;
            uint32_t st = sbase + SM_HDR_B + s*STAGE_H*2;
            mbar_expect(mb, STAGE_H*2);
            bulk_cp(st,             Asrc + (size_t)s*A_ROWH, A_ROWH*2, mb);
            bulk_cp(st + A_ROWH*2,  Bsrc + (size_t)s*B_ROWH, B_ROWH*2, mb);
        }
    }

    float acc[4][4][4];
    #pragma unroll
    for (int mt = 0; mt < 4; mt++)
        #pragma unroll
        for (int nt = 0; nt < 4; nt++)
            #pragma unroll
            for (int q = 0; q < 4; q++) acc[mt][nt][q] = 0.0f;

    for (int kt = 0; kt < 8; kt++) {
        const int s = kt % NSTAGE;
        __syncthreads();
        if (tid == 0 && kt + 2 < 8) {
            const int s2 = (kt + 2) % NSTAGE;
            uint32_t mb = sbase + s2*8;
            uint32_t st = sbase + SM_HDR_B + s2*STAGE_H*2;
            mbar_expect(mb, STAGE_H*2);
            bulk_cp(st,            Asrc + (size_t)(kt+2)*A_ROWH, A_ROWH*2, mb);
            bulk_cp(st + A_ROWH*2, Bsrc + (size_t)(kt+2)*B_ROWH, B_ROWH*2, mb);
        }
        mbar_wait(sbase + s*8, (kt / NSTAGE) & 1);

        const __half* sA = smh + s*STAGE_H;
        const __half* sB = sA + A_ROWH;

        #pragma unroll
        for (int g16 = 0; g16 < 4; g16++) {
            const int off = g16*16 + 4*ctib;
            uint2 alo[4], ahi[4], bfr[4];
            #pragma unroll
            for (int mt = 0; mt < 4; mt++) {
                const __half* pa = sA + (wm0 + mt*16 + g)*LDTH + off;
                alo[mt] = *(const uint2*)pa;
                ahi[mt] = *(const uint2*)(pa + 8*LDTH);
            }
            #pragma unroll
            for (int nt = 0; nt < 4; nt++)
                bfr[nt] = *(const uint2*)(sB + (wn0 + nt*8 + g)*LDTH + off);

            #pragma unroll
            for (int mt = 0; mt < 4; mt++)
                #pragma unroll
                for (int nt = 0; nt < 4; nt++)
                    mma_f16(acc[mt][nt],
                            alo[mt].x, ahi[mt].x, alo[mt].y, ahi[mt].y,
                            bfr[nt].x, bfr[nt].y);
        }
    }
    __syncthreads();

    // -------- epilogue: BN + ReLU --------
    if (mode == 0) {
        // write Y_tiled (half). Warp covers k-range of exactly ktile kt0.
        __half* patch = (__half*)(smraw + SM_HDR_B) + wid * 2304;   // 32 x 72 halves
        #pragma unroll
        for (int mt = 0; mt < 4; mt++) {
            const int o0 = m0 + wm0 + mt*16 + g;
            const float sc0 = G[o0]   * rsqrtf(Va[o0]   + 1e-5f);
            const float sh0 = Bb[o0]   - Mu[o0]  * sc0;
            const float sc1 = G[o0+8] * rsqrtf(Va[o0+8] + 1e-5f);
            const float sh1 = Bb[o0+8] - Mu[o0+8] * sc1;
            const int ml  = kpos64(mt*16 + g);
            const int mlh = kpos64(mt*16 + g + 8);
            #pragma unroll
            for (int nt = 0; nt < 4; nt++) {
                const int nl = nt*8 + 2*ctib;
                patch[ nl   *72 + ml ] = __float2half_rn(fmaxf(fmaf(acc[mt][nt][0], sc0, sh0), 0.f));
                patch[(nl+1)*72 + ml ] = __float2half_rn(fmaxf(fmaf(acc[mt][nt][1], sc0, sh0), 0.f));
                patch[ nl   *72 + mlh] = __float2half_rn(fmaxf(fmaf(acc[mt][nt][2], sc1, sh1), 0.f));
                patch[(nl+1)*72 + mlh] = __float2half_rn(fmaxf(fmaf(acc[mt][nt][3], sc1, sh1), 0.f));
            }
        }
        __syncwarp();
        const int kt0 = (m0 + wm0) >> 6;
        __half* yb = (__half*)OutV + (size_t)(nblk * 8 + kt0) * B_ROWH + wn0 * LDTH + lane*2;
        #pragma unroll
        for (int r = 0; r < 32; r++)
            *(__half2*)(yb + r * LDTH) = *(__half2*)(patch + r*72 + lane*2);
    } else {
        // write d_out (B,512,8192) fp32
        float* patch = (float*)(smraw + SM_HDR_B) + wid * 2304;     // 64 x 36 floats
        #pragma unroll
        for (int mt = 0; mt < 4; mt++) {
            const int o0 = m0 + wm0 + mt*16 + g;
            const float sc0 = G[o0]   * rsqrtf(Va[o0]   + 1e-5f);
            const float sh0 = Bb[o0]   - Mu[o0]  * sc0;
            const float sc1 = G[o0+8] * rsqrtf(Va[o0+8] + 1e-5f);
            const float sh1 = Bb[o0+8] - Mu[o0+8] * sc1;
            const int ml = mt*16 + g;
            #pragma unroll
            for (int nt = 0; nt < 4; nt++) {
                const int nl = nt*8 + 2*ctib;
                patch[ ml   *36 + nl  ] = fmaxf(fmaf(acc[mt][nt][0], sc0, sh0), 0.f);
                patch[ ml   *36 + nl+1] = fmaxf(fmaf(acc[mt][nt][1], sc0, sh0), 0.f);
                patch[(ml+8)*36 + nl  ] = fmaxf(fmaf(acc[mt][nt][2], sc1, sh1), 0.f);
                patch[(ml+8)*36 + nl+1] = fmaxf(fmaf(acc[mt][nt][3], sc1, sh1), 0.f);
            }
        }
        __syncwarp();
        const int b  = n0 >> 13;
        const int j0 = (n0 & (NPT-1)) + wn0;
        float* ob = (float*)OutV + ((size_t)b * H_ + m0 + wm0) * NPT + j0;
        #pragma unroll
        for (int r = 0; r < 64; r++)
            ob[(size_t)r * NPT + lane] = patch[r*36 + lane];
    }
}

// ---------------- launch ----------------
extern "C" void kernel_launch(void* const* d_in, const int* in_sizes, int n_in,
                              void* d_out, int out_size)
{
    const float* unknown      = (const float*)d_in[0];
    const float* known        = (const float*)d_in[1];
    const float* unknow_feats = (const float*)d_in[2];
    const float* known_feats  = (const float*)d_in[3];
    const float* W1 = (const float*)d_in[4];
    const float* g1 = (const float*)d_in[5];
    const float* b1 = (const float*)d_in[6];
    const float* m1 = (const float*)d_in[7];
    const float* v1 = (const float*)d_in[8];
    const float* W2 = (const float*)d_in[9];
    const float* g2 = (const float*)d_in[10];
    const float* b2 = (const float*)d_in[11];
    const float* m2 = (const float*)d_in[12];
    const float* v2 = (const float*)d_in[13];
    float* out = (float*)d_out;

    __half* Xt;  cudaGetSymbolAddress((void**)&Xt,  g_Xt);
    __half* Yt;  cudaGetSymbolAddress((void**)&Yt,  g_Yt);
    __half* W1t; cudaGetSymbolAddress((void**)&W1t, g_W1t);
    __half* W2t; cudaGetSymbolAddress((void**)&W2t, g_W2t);

    cudaFuncSetAttribute(gemm_tc, cudaFuncAttributeMaxDynamicSharedMemorySize, SMEMBT);

    prep_kernel<<<1024 + 4096 + 16384, 256>>>(W1, W2, known_feats, unknow_feats);
    knn_kernel<<<dim3(NPT/256, B_), 256>>>(unknown, known);
    interp_kernel<<<NTOT/8, 256>>>();

    gemm_tc<<<dim3(4, 256), 512, SMEMBT>>>(W1t, Xt, Yt,  g1, b1, m1, v1, 0);
    gemm_tc<<<dim3(4, 256), 512, SMEMBT>>>(W2t, Yt, out, g2, b2, m2, v2, 1);

    (void)in_sizes; (void)n_in; (void)out_size;
}

// round 9
// speedup vs baseline: 1.8355x; 1.1351x over previous
#include <cuda_runtime.h>
#include <cuda_fp16.h>
#include <cstdint>
#include <math.h>

#define B_    8
#define NPT   8192
#define MPT   2048
#define C_    256
#define H_    512
#define NTOT  (B_*NPT)

// GEMM tiling: BM=128, BN=128, BK=64 halves, rows are exactly 64 halves (128 B), XOR-swizzled
#define A_TH    8192                        // 128*64 halves = 16 KB
#define B_TH    8192
#define STG_H   (A_TH + B_TH)               // 16384 halves = 32 KB
#define NST     3
#define HDR_B   128
#define SMB     (HDR_B + NST*STG_H*2)       // 98432 B -> 2 CTAs/SM

// ---------------- scratch: tiled fp16 operands ----------------
// X/Y tiled: [nblk 512][ktile 8][row 128][64]
__device__ __align__(1024) __half g_Xt[(size_t)512 * 8 * B_TH];
__device__ __align__(1024) __half g_Yt[(size_t)512 * 8 * B_TH];
// W tiled:   [mblk 4][ktile 8][row 128][64]
__device__ __align__(1024) __half g_W1t[4 * 8 * A_TH];
__device__ __align__(1024) __half g_W2t[4 * 8 * A_TH];
__device__ float  g_kft[(size_t)B_ * MPT * C_];
__device__ int    g_idx[NTOT * 3];
__device__ float  g_w[NTOT * 3];

// k-local position within 64-half row: pair-interleave per 16-group (fragment packing)
__device__ __forceinline__ int kpos64(int l) {
    int p  = (l >> 1) & 7;
    int pp = ((p & 3) << 1) | (p >> 2);
    return (l & ~15) | (pp << 1) | (l & 1);
}
// full physical position: kpos then XOR 8B-unit swizzle by row
__device__ __forceinline__ int spos(int r, int l) {
    int b = kpos64(l);
    return ((((b >> 2) ^ ((r & 3) << 2)) << 2) | (b & 3));
}
__device__ __forceinline__ uint32_t smem_u32(const void* p) {
    uint32_t a;
    asm("{ .reg .u64 t; cvta.to.shared.u64 t, %1; cvt.u32.u64 %0, t; }" : "=r"(a) : "l"(p));
    return a;
}
__device__ __forceinline__ void bulk_cp(uint32_t dst, const void* src, uint32_t bytes, uint32_t mbar) {
    asm volatile("cp.async.bulk.shared::cta.global.mbarrier::complete_tx::bytes [%0], [%1], %2, [%3];"
                 :: "r"(dst), "l"(src), "r"(bytes), "r"(mbar) : "memory");
}
__device__ __forceinline__ void mbar_init(uint32_t a, uint32_t cnt) {
    asm volatile("mbarrier.init.shared.b64 [%0], %1;" :: "r"(a), "r"(cnt) : "memory");
}
__device__ __forceinline__ void mbar_expect(uint32_t a, uint32_t bytes) {
    asm volatile("mbarrier.arrive.expect_tx.shared.b64 _, [%0], %1;" :: "r"(a), "r"(bytes) : "memory");
}
__device__ __forceinline__ void mbar_wait(uint32_t a, uint32_t ph) {
    asm volatile("{\n\t.reg .pred P;\n\tWL%=:\n\t"
                 "mbarrier.try_wait.parity.acquire.cta.shared::cta.b64 P, [%0], %1, 0x989680;\n\t"
                 "@!P bra WL%=;\n\t}" :: "r"(a), "r"(ph) : "memory");
}

// ---------------- fused prep: W->tiled f16 + tr_kf + tr_uf->X_tiled f16 ----------------
__global__ __launch_bounds__(256)
void prep_kernel(const float* __restrict__ W1, const float* __restrict__ W2,
                 const float* __restrict__ kf, const float* __restrict__ uf)
{
    __shared__ float t[32][33];
    const int bid = blockIdx.x;
    const int tid = threadIdx.x;

    if (bid < 1024) {
        int i = bid * 256 + tid;
        int o = i >> 9, k = i & 511;
        int row = o & 127;
        size_t a = (size_t)((o >> 7) * 8 + (k >> 6)) * A_TH + row * 64 + spos(row, k & 63);
        g_W1t[a] = __float2half_rn(W1[i]);
        g_W2t[a] = __float2half_rn(W2[i]);
        return;
    }
    const int x = tid & 31, y0 = tid >> 5;
    if (bid < 1024 + 4096) {
        const int idx = bid - 1024;
        const int m0 = (idx & 63) * 32;
        const int c0 = ((idx >> 6) & 7) * 32;
        const int b  = idx >> 9;
        #pragma unroll
        for (int yy = 0; yy < 32; yy += 8)
            t[y0+yy][x] = kf[((size_t)b*C_ + c0+y0+yy)*MPT + m0 + x];
        __syncthreads();
        #pragma unroll
        for (int yy = 0; yy < 32; yy += 8)
            g_kft[((size_t)b*MPT + m0 + y0+yy)*C_ + c0 + x] = t[x][y0+yy];
    } else {
        const int idx = bid - 1024 - 4096;
        const int j0 = (idx & 255) * 32;
        const int c0 = ((idx >> 8) & 7) * 32;
        const int b  = idx >> 11;
        #pragma unroll
        for (int yy = 0; yy < 32; yy += 8)
            t[y0+yy][x] = uf[((size_t)b*C_ + c0+y0+yy)*NPT + j0 + x];
        __syncthreads();
        const int ch = C_ + c0 + x;
        const int kt = ch >> 6;
        const int kl = ch & 63;
        #pragma unroll
        for (int yy = 0; yy < 32; yy += 8) {
            const int p = b * NPT + j0 + y0 + yy;
            const int row = p & 127;
            g_Xt[(size_t)((p >> 7) * 8 + kt) * B_TH + row * 64 + spos(row, kl)] =
                __float2half_rn(t[x][y0+yy]);
        }
    }
}

// ---------------- 3-NN + weights ----------------
__global__ __launch_bounds__(256)
void knn_kernel(const float* __restrict__ unknown, const float* __restrict__ known)
{
    __shared__ float kx[MPT], ky[MPT], kz[MPT];
    const int b = blockIdx.y;
    const float* kb = known + (size_t)b * MPT * 3;
    for (int i = threadIdx.x; i < MPT; i += 256) {
        kx[i] = kb[i*3+0]; ky[i] = kb[i*3+1]; kz[i] = kb[i*3+2];
    }
    __syncthreads();

    const int q = blockIdx.x * 256 + threadIdx.x;
    const float* up = unknown + ((size_t)b * NPT + q) * 3;
    const float ux = up[0], uy = up[1], uz = up[2];

    float d0 = 1e30f, d1 = 1e30f, d2 = 1e30f;
    int   i0 = 0,     i1 = 0,     i2 = 0;
    #pragma unroll 4
    for (int i = 0; i < MPT; i++) {
        float dx = kx[i]-ux, dy = ky[i]-uy, dz = kz[i]-uz;
        float d = dx*dx + dy*dy + dz*dz;
        if (d < d2) {
            if (d < d1) {
                if (d < d0) { d2=d1; i2=i1; d1=d0; i1=i0; d0=d; i0=i; }
                else        { d2=d1; i2=i1; d1=d;  i1=i; }
            } else          { d2=d;  i2=i; }
        }
    }
    const float r0 = 1.f/(d0+1e-8f), r1 = 1.f/(d1+1e-8f), r2 = 1.f/(d2+1e-8f);
    const float s = 1.f/(r0+r1+r2);
    const int gi = b * NPT + q;
    g_idx[gi*3+0] = i0; g_idx[gi*3+1] = i1; g_idx[gi*3+2] = i2;
    g_w[gi*3+0] = r0*s; g_w[gi*3+1] = r1*s; g_w[gi*3+2] = r2*s;
}

// ---------------- interpolate -> X_tiled f16 (channels 0..255); warp per point ----------------
__global__ __launch_bounds__(256)
void interp_kernel()
{
    const int p = blockIdx.x * 8 + (threadIdx.x >> 5);
    const int lane = threadIdx.x & 31;
    const int b = p >> 13;

    const int   i0 = g_idx[p*3+0], i1 = g_idx[p*3+1], i2 = g_idx[p*3+2];
    const float w0 = g_w[p*3+0],   w1 = g_w[p*3+1],   w2 = g_w[p*3+2];

    const float* r0 = g_kft + ((size_t)b*MPT + i0)*C_ + lane*8;
    const float* r1 = g_kft + ((size_t)b*MPT + i1)*C_ + lane*8;
    const float* r2 = g_kft + ((size_t)b*MPT + i2)*C_ + lane*8;

    float4 a0 = *(const float4*)r0, a1 = *(const float4*)(r0+4);
    float4 c0 = *(const float4*)r1, c1 = *(const float4*)(r1+4);
    float4 e0 = *(const float4*)r2, e1 = *(const float4*)(r2+4);

    float v[8];
    v[0] = w0*a0.x + w1*c0.x + w2*e0.x;
    v[1] = w0*a0.y + w1*c0.y + w2*e0.y;
    v[2] = w0*a0.z + w1*c0.z + w2*e0.z;
    v[3] = w0*a0.w + w1*c0.w + w2*e0.w;
    v[4] = w0*a1.x + w1*c1.x + w2*e1.x;
    v[5] = w0*a1.y + w1*c1.y + w2*e1.y;
    v[6] = w0*a1.z + w1*c1.z + w2*e1.z;
    v[7] = w0*a1.w + w1*c1.w + w2*e1.w;

    // channels ch = lane*8 + t ; ktile = lane>>3 ; l = (lane&7)*8 + t ; row = p&127
    const int row = p & 127;
    __half* xp = g_Xt + (size_t)((p >> 7) * 8 + (lane >> 3)) * B_TH + row * 64;
    const int base = (lane & 7) * 8;
    #pragma unroll
    for (int t = 0; t < 8; t++)
        xp[spos(row, base + t)] = __float2half_rn(v[t]);
}

// ---------------- fp16 mma.sync GEMM: BM=128 BN=128 BK=64, 256 thr, 2 CTAs/SM ----------------
__device__ __forceinline__ void mma_f16(float* c, uint32_t a0, uint32_t a1, uint32_t a2, uint32_t a3,
                                        uint32_t b0, uint32_t b1)
{
    asm volatile(
        "mma.sync.aligned.m16n8k16.row.col.f32.f16.f16.f32 "
        "{%0,%1,%2,%3}, {%4,%5,%6,%7}, {%8,%9}, {%0,%1,%2,%3};"
        : "+f"(c[0]), "+f"(c[1]), "+f"(c[2]), "+f"(c[3])
        : "r"(a0), "r"(a1), "r"(a2), "r"(a3), "r"(b0), "r"(b1));
}

__global__ __launch_bounds__(256, 2)
void gemm_tc(const __half* __restrict__ Wt, const __half* __restrict__ Bt, void* __restrict__ OutV,
             const float* __restrict__ G, const float* __restrict__ Bb,
             const float* __restrict__ Mu, const float* __restrict__ Va, int mode)
{
    extern __shared__ char smraw[];
    __half* smh = (__half*)(smraw + HDR_B);
    const uint32_t sbase = smem_u32(smraw);
    const int tid  = threadIdx.x;
    const int wid  = tid >> 5;             // 0..7
    const int lane = tid & 31;
    const int g    = lane >> 2;
    const int ctib = lane & 3;
    const int wm0  = (wid >> 2) * 64;      // 0 or 64
    const int wn0  = (wid & 3)  * 32;      // 0..96
    const int mblk = blockIdx.x;           // 0..3 fastest -> 4 CTAs share B tile via L2
    const int nblk = blockIdx.y;           // 0..511
    const int m0   = mblk * 128;
    const int n0   = nblk * 128;

    if (tid == 0) {
        mbar_init(sbase + 0, 1);
        mbar_init(sbase + 8, 1);
        mbar_init(sbase + 16, 1);
    }
    __syncthreads();

    const __half* Asrc = Wt + (size_t)mblk * 8 * A_TH;
    const __half* Bsrc = Bt + (size_t)nblk * 8 * B_TH;

    if (tid == 0) {
        #pragma unroll
        for (int s = 0; s < 2; s++) {
            uint32_t mb = sbase + s*8;
            uint32_t st = sbase + HDR_B + s*STG_H*2;
            mbar_expect(mb, STG_H*2);
            bulk_cp(st,           Asrc + (size_t)s*A_TH, A_TH*2, mb);
            bulk_cp(st + A_TH*2,  Bsrc + (size_t)s*B_TH, B_TH*2, mb);
        }
    }

    float acc[4][4][4];
    #pragma unroll
    for (int mt = 0; mt < 4; mt++)
        #pragma unroll
        for (int nt = 0; nt < 4; nt++)
            #pragma unroll
            for (int q = 0; q < 4; q++) acc[mt][nt][q] = 0.0f;

    const int gx = (g & 3) << 2;           // XOR term for this lane's rows

    for (int kt = 0; kt < 8; kt++) {
        const int s = kt % NST;
        __syncthreads();
        if (tid == 0 && kt + 2 < 8) {
            const int s2 = (kt + 2) % NST;
            uint32_t mb = sbase + s2*8;
            uint32_t st = sbase + HDR_B + s2*STG_H*2;
            mbar_expect(mb, STG_H*2);
            bulk_cp(st,          Asrc + (size_t)(kt+2)*A_TH, A_TH*2, mb);
            bulk_cp(st + A_TH*2, Bsrc + (size_t)(kt+2)*B_TH, B_TH*2, mb);
        }
        mbar_wait(sbase + s*8, (kt / NST) & 1);

        const __half* sA = smh + s*STG_H;
        const __half* sB = sA + A_TH;

        #pragma unroll
        for (int g16 = 0; g16 < 4; g16++) {
            const int ua = ((ctib + 4*g16) ^ gx) * 4;    // swizzled unit -> half offset
            uint2 alo[4], ahi[4], bfr[4];
            #pragma unroll
            for (int mt = 0; mt < 4; mt++) {
                const __half* pa = sA + (wm0 + mt*16 + g)*64 + ua;
                alo[mt] = *(const uint2*)pa;
                ahi[mt] = *(const uint2*)(pa + 8*64);
            }
            #pragma unroll
            for (int nt = 0; nt < 4; nt++)
                bfr[nt] = *(const uint2*)(sB + (wn0 + nt*8 + g)*64 + ua);

            #pragma unroll
            for (int mt = 0; mt < 4; mt++)
                #pragma unroll
                for (int nt = 0; nt < 4; nt++)
                    mma_f16(acc[mt][nt],
                            alo[mt].x, ahi[mt].x, alo[mt].y, ahi[mt].y,
                            bfr[nt].x, bfr[nt].y);
        }
    }
    __syncthreads();

    // -------- epilogue: BN + ReLU --------
    if (mode == 0) {
        // write Y_tiled (half): warp covers ktile kt0 of rows n0..n0+127
        __half* patch = (__half*)(smraw + HDR_B) + wid * 2304;   // 32 x 72 halves
        #pragma unroll
        for (int mt = 0; mt < 4; mt++) {
            const int o0 = m0 + wm0 + mt*16 + g;
            const float sc0 = G[o0]   * rsqrtf(Va[o0]   + 1e-5f);
            const float sh0 = Bb[o0]   - Mu[o0]  * sc0;
            const float sc1 = G[o0+8] * rsqrtf(Va[o0+8] + 1e-5f);
            const float sh1 = Bb[o0+8] - Mu[o0+8] * sc1;
            const int ml  = kpos64(mt*16 + g);
            const int mlh = kpos64(mt*16 + g + 8);
            #pragma unroll
            for (int nt = 0; nt < 4; nt++) {
                const int nl = nt*8 + 2*ctib;
                patch[ nl   *72 + ml ] = __float2half_rn(fmaxf(fmaf(acc[mt][nt][0], sc0, sh0), 0.f));
                patch[(nl+1)*72 + ml ] = __float2half_rn(fmaxf(fmaf(acc[mt][nt][1], sc0, sh0), 0.f));
                patch[ nl   *72 + mlh] = __float2half_rn(fmaxf(fmaf(acc[mt][nt][2], sc1, sh1), 0.f));
                patch[(nl+1)*72 + mlh] = __float2half_rn(fmaxf(fmaf(acc[mt][nt][3], sc1, sh1), 0.f));
            }
        }
        __syncwarp();
        const int kt0 = (m0 + wm0) >> 6;
        __half* yb = (__half*)OutV + (size_t)(nblk * 8 + kt0) * B_TH + wn0 * 64;
        #pragma unroll
        for (int rr = 0; rr < 32; rr++) {
            // patch holds kpos-ordered halves; apply row-XOR on 8B units at the write
            const int off = (((lane >> 1) ^ ((rr & 3) << 2)) << 2) + (lane & 1) * 2;
            *(__half2*)(yb + rr*64 + off) = *(__half2*)(patch + rr*72 + lane*2);
        }
    } else {
        // write d_out (B,512,8192) fp32
        float* patch = (float*)(smraw + HDR_B) + wid * 2304;     // 64 x 36 floats
        #pragma unroll
        for (int mt = 0; mt < 4; mt++) {
            const int o0 = m0 + wm0 + mt*16 + g;
            const float sc0 = G[o0]   * rsqrtf(Va[o0]   + 1e-5f);
            const float sh0 = Bb[o0]   - Mu[o0]  * sc0;
            const float sc1 = G[o0+8] * rsqrtf(Va[o0+8] + 1e-5f);
            const float sh1 = Bb[o0+8] - Mu[o0+8] * sc1;
            const int ml = mt*16 + g;
            #pragma unroll
            for (int nt = 0; nt < 4; nt++) {
                const int nl = nt*8 + 2*ctib;
                patch[ ml   *36 + nl  ] = fmaxf(fmaf(acc[mt][nt][0], sc0, sh0), 0.f);
                patch[ ml   *36 + nl+1] = fmaxf(fmaf(acc[mt][nt][1], sc0, sh0), 0.f);
                patch[(ml+8)*36 + nl  ] = fmaxf(fmaf(acc[mt][nt][2], sc1, sh1), 0.f);
                patch[(ml+8)*36 + nl+1] = fmaxf(fmaf(acc[mt][nt][3], sc1, sh1), 0.f);
            }
        }
        __syncwarp();
        const int b  = n0 >> 13;
        const int j0 = (n0 & (NPT-1)) + wn0;
        float* ob = (float*)OutV + ((size_t)b * H_ + m0 + wm0) * NPT + j0;
        #pragma unroll
        for (int r = 0; r < 64; r++)
            ob[(size_t)r * NPT + lane] = patch[r*36 + lane];
    }
}

// ---------------- launch ----------------
extern "C" void kernel_launch(void* const* d_in, const int* in_sizes, int n_in,
                              void* d_out, int out_size)
{
    const float* unknown      = (const float*)d_in[0];
    const float* known        = (const float*)d_in[1];
    const float* unknow_feats = (const float*)d_in[2];
    const float* known_feats  = (const float*)d_in[3];
    const float* W1 = (const float*)d_in[4];
    const float* g1 = (const float*)d_in[5];
    const float* b1 = (const float*)d_in[6];
    const float* m1 = (const float*)d_in[7];
    const float* v1 = (const float*)d_in[8];
    const float* W2 = (const float*)d_in[9];
    const float* g2 = (const float*)d_in[10];
    const float* b2 = (const float*)d_in[11];
    const float* m2 = (const float*)d_in[12];
    const float* v2 = (const float*)d_in[13];
    float* out = (float*)d_out;

    __half* Xt;  cudaGetSymbolAddress((void**)&Xt,  g_Xt);
    __half* Yt;  cudaGetSymbolAddress((void**)&Yt,  g_Yt);
    __half* W1t; cudaGetSymbolAddress((void**)&W1t, g_W1t);
    __half* W2t; cudaGetSymbolAddress((void**)&W2t, g_W2t);

    cudaFuncSetAttribute(gemm_tc, cudaFuncAttributeMaxDynamicSharedMemorySize, SMB);

    prep_kernel<<<1024 + 4096 + 16384, 256>>>(W1, W2, known_feats, unknow_feats);
    knn_kernel<<<dim3(NPT/256, B_), 256>>>(unknown, known);
    interp_kernel<<<NTOT/8, 256>>>();

    gemm_tc<<<dim3(4, 512), 256, SMB>>>(W1t, Xt, Yt,  g1, b1, m1, v1, 0);
    gemm_tc<<<dim3(4, 512), 256, SMB>>>(W2t, Yt, out, g2, b2, m2, v2, 1);

    (void)in_sizes; (void)n_in; (void)out_size;
}

// round 10
// speedup vs baseline: 1.9366x; 1.0551x over previous
#include <cuda_runtime.h>
#include <cuda_fp16.h>
#include <cstdint>
#include <math.h>

#define B_    8
#define NPT   8192
#define MPT   2048
#define C_    256
#define H_    512
#define NTOT  (B_*NPT)

// GEMM tiling: BM=128, BN=128, BK=64 halves, rows 64 halves (128 B), XOR-swizzled
#define A_TH    8192
#define B_TH    8192
#define STG_H   (A_TH + B_TH)
#define NST     3
#define HDR_B   128
#define SMB     (HDR_B + NST*STG_H*2)       // 98432 B -> 2 CTAs/SM

// ---------------- scratch ----------------
__device__ __align__(1024) __half g_Xt[(size_t)512 * 8 * B_TH];
__device__ __align__(1024) __half g_Yt[(size_t)512 * 8 * B_TH];
__device__ __align__(1024) __half g_W1t[4 * 8 * A_TH];
__device__ __align__(1024) __half g_W2t[4 * 8 * A_TH];
__device__ float  g_kft[(size_t)B_ * MPT * C_];
__device__ int    g_idx[NTOT * 3];
__device__ float  g_w[NTOT * 3];

__device__ __forceinline__ int kpos64(int l) {
    int p  = (l >> 1) & 7;
    int pp = ((p & 3) << 1) | (p >> 2);
    return (l & ~15) | (pp << 1) | (l & 1);
}
__device__ __forceinline__ int spos(int r, int l) {
    int b = kpos64(l);
    return ((((b >> 2) ^ ((r & 3) << 2)) << 2) | (b & 3));
}
__device__ __forceinline__ uint32_t smem_u32(const void* p) {
    uint32_t a;
    asm("{ .reg .u64 t; cvta.to.shared.u64 t, %1; cvt.u32.u64 %0, t; }" : "=r"(a) : "l"(p));
    return a;
}
__device__ __forceinline__ void bulk_cp(uint32_t dst, const void* src, uint32_t bytes, uint32_t mbar) {
    asm volatile("cp.async.bulk.shared::cta.global.mbarrier::complete_tx::bytes [%0], [%1], %2, [%3];"
                 :: "r"(dst), "l"(src), "r"(bytes), "r"(mbar) : "memory");
}
__device__ __forceinline__ void mbar_init(uint32_t a, uint32_t cnt) {
    asm volatile("mbarrier.init.shared.b64 [%0], %1;" :: "r"(a), "r"(cnt) : "memory");
}
__device__ __forceinline__ void mbar_expect(uint32_t a, uint32_t bytes) {
    asm volatile("mbarrier.arrive.expect_tx.shared.b64 _, [%0], %1;" :: "r"(a), "r"(bytes) : "memory");
}
__device__ __forceinline__ void mbar_wait(uint32_t a, uint32_t ph) {
    asm volatile("{\n\t.reg .pred P;\n\tWL%=:\n\t"
                 "mbarrier.try_wait.parity.acquire.cta.shared::cta.b64 P, [%0], %1, 0x989680;\n\t"
                 "@!P bra WL%=;\n\t}" :: "r"(a), "r"(ph) : "memory");
}

// ---------------- fused prep: W->tiled f16 + tr_kf + tr_uf->X_tiled f16 ----------------
__global__ __launch_bounds__(256)
void prep_kernel(const float* __restrict__ W1, const float* __restrict__ W2,
                 const float* __restrict__ kf, const float* __restrict__ uf)
{
    __shared__ float t[32][33];
    const int bid = blockIdx.x;
    const int tid = threadIdx.x;

    if (bid < 1024) {
        int i = bid * 256 + tid;
        int o = i >> 9, k = i & 511;
        int row = o & 127;
        size_t a = (size_t)((o >> 7) * 8 + (k >> 6)) * A_TH + row * 64 + spos(row, k & 63);
        g_W1t[a] = __float2half_rn(W1[i]);
        g_W2t[a] = __float2half_rn(W2[i]);
        return;
    }
    const int x = tid & 31, y0 = tid >> 5;
    if (bid < 1024 + 4096) {
        const int idx = bid - 1024;
        const int m0 = (idx & 63) * 32;
        const int c0 = ((idx >> 6) & 7) * 32;
        const int b  = idx >> 9;
        #pragma unroll
        for (int yy = 0; yy < 32; yy += 8)
            t[y0+yy][x] = kf[((size_t)b*C_ + c0+y0+yy)*MPT + m0 + x];
        __syncthreads();
        #pragma unroll
        for (int yy = 0; yy < 32; yy += 8)
            g_kft[((size_t)b*MPT + m0 + y0+yy)*C_ + c0 + x] = t[x][y0+yy];
    } else {
        const int idx = bid - 1024 - 4096;
        const int j0 = (idx & 255) * 32;
        const int c0 = ((idx >> 8) & 7) * 32;
        const int b  = idx >> 11;
        #pragma unroll
        for (int yy = 0; yy < 32; yy += 8)
            t[y0+yy][x] = uf[((size_t)b*C_ + c0+y0+yy)*NPT + j0 + x];
        __syncthreads();
        const int ch = C_ + c0 + x;
        const int kt = ch >> 6;
        const int kl = ch & 63;
        #pragma unroll
        for (int yy = 0; yy < 32; yy += 8) {
            const int p = b * NPT + j0 + y0 + yy;
            const int row = p & 127;
            g_Xt[(size_t)((p >> 7) * 8 + kt) * B_TH + row * 64 + spos(row, kl)] =
                __float2half_rn(t[x][y0+yy]);
        }
    }
}

// ---------------- 3-NN + weights (3-FMA inner loop) ----------------
__global__ __launch_bounds__(256)
void knn_kernel(const float* __restrict__ unknown, const float* __restrict__ known)
{
    __shared__ float kx[MPT], ky[MPT], kz[MPT], kk[MPT];
    const int b = blockIdx.y;
    const float* kb = known + (size_t)b * MPT * 3;
    for (int i = threadIdx.x; i < MPT; i += 256) {
        float x = kb[i*3+0], y = kb[i*3+1], z = kb[i*3+2];
        kx[i] = x; ky[i] = y; kz[i] = z;
        kk[i] = x*x + y*y + z*z;
    }
    __syncthreads();

    const int q = blockIdx.x * 256 + threadIdx.x;
    const float* up = unknown + ((size_t)b * NPT + q) * 3;
    const float ux = up[0], uy = up[1], uz = up[2];
    const float ax = -2.f*ux, ay = -2.f*uy, az = -2.f*uz;
    const float uu = ux*ux + uy*uy + uz*uz;

    float d0 = 1e30f, d1 = 1e30f, d2 = 1e30f;
    int   i0 = 0,     i1 = 0,     i2 = 0;
    #pragma unroll 4
    for (int i = 0; i < MPT; i++) {
        // d' = |k|^2 - 2 u.k  (monotone shift of |u-k|^2 by constant |u|^2)
        float d = fmaf(kx[i], ax, fmaf(ky[i], ay, fmaf(kz[i], az, kk[i])));
        if (d < d2) {
            if (d < d1) {
                if (d < d0) { d2=d1; i2=i1; d1=d0; i1=i0; d0=d; i0=i; }
                else        { d2=d1; i2=i1; d1=d;  i1=i; }
            } else          { d2=d;  i2=i; }
        }
    }
    d0 += uu; d1 += uu; d2 += uu;
    const float r0 = 1.f/(d0+1e-8f), r1 = 1.f/(d1+1e-8f), r2 = 1.f/(d2+1e-8f);
    const float s = 1.f/(r0+r1+r2);
    const int gi = b * NPT + q;
    g_idx[gi*3+0] = i0; g_idx[gi*3+1] = i1; g_idx[gi*3+2] = i2;
    g_w[gi*3+0] = r0*s; g_w[gi*3+1] = r1*s; g_w[gi*3+2] = r2*s;
}

// ---------------- interpolate -> X_tiled f16, smem-staged coalesced stores ----------------
// Block = 32 points. Phase 1: warp-per-point gather+interp -> smem (kpos-ordered halves).
// Phase 2: ST.128 rows; 16B chunks stay 16B chunks under the row-XOR swizzle.
__global__ __launch_bounds__(256)
void interp_kernel()
{
    __shared__ __align__(16) __half sbuf[32][264];
    const int tid  = threadIdx.x;
    const int wid  = tid >> 5;
    const int lane = tid & 31;
    const int p0   = blockIdx.x * 32;

    #pragma unroll
    for (int it = 0; it < 4; it++) {
        const int s = wid * 4 + it;
        const int p = p0 + s;
        const int b = p >> 13;

        const int   i0 = g_idx[p*3+0], i1 = g_idx[p*3+1], i2 = g_idx[p*3+2];
        const float w0 = g_w[p*3+0],   w1 = g_w[p*3+1],   w2 = g_w[p*3+2];

        const float* r0 = g_kft + ((size_t)b*MPT + i0)*C_ + lane*8;
        const float* r1 = g_kft + ((size_t)b*MPT + i1)*C_ + lane*8;
        const float* r2 = g_kft + ((size_t)b*MPT + i2)*C_ + lane*8;

        float4 a0 = *(const float4*)r0, a1 = *(const float4*)(r0+4);
        float4 c0 = *(const float4*)r1, c1 = *(const float4*)(r1+4);
        float4 e0 = *(const float4*)r2, e1 = *(const float4*)(r2+4);

        float v[8];
        v[0] = w0*a0.x + w1*c0.x + w2*e0.x;
        v[1] = w0*a0.y + w1*c0.y + w2*e0.y;
        v[2] = w0*a0.z + w1*c0.z + w2*e0.z;
        v[3] = w0*a0.w + w1*c0.w + w2*e0.w;
        v[4] = w0*a1.x + w1*c1.x + w2*e1.x;
        v[5] = w0*a1.y + w1*c1.y + w2*e1.y;
        v[6] = w0*a1.z + w1*c1.z + w2*e1.z;
        v[7] = w0*a1.w + w1*c1.w + w2*e1.w;

        // channels ch = lane*8 + t -> ktile lane>>3, local l = (lane&7)*8 + t
        __half* sp = &sbuf[s][(lane >> 3) * 64];
        const int base = (lane & 7) * 8;
        #pragma unroll
        for (int t = 0; t < 4; t++) {
            const int pos = kpos64(base + 2*t);       // even, pair-adjacent
            *(__half2*)(sp + pos) = __floats2half2_rn(v[2*t], v[2*t+1]);
        }
    }
    __syncthreads();

    // Phase 2: 32 pts x 4 ktiles = 128 rows x 128 B; 8 chunks/row; 4 iters x 256 thr
    #pragma unroll
    for (int it = 0; it < 4; it++) {
        const int id  = it * 256 + tid;
        const int row = id >> 3;
        const int c   = id & 7;
        const int s   = row >> 2;
        const int kt  = row & 3;
        const int p   = p0 + s;
        const int r   = p & 127;
        const int xr  = (r & 3) << 2;
        uint4 val = *(const uint4*)(&sbuf[s][kt*64 + c*8]);
        __half* dst = g_Xt + (size_t)((p >> 7) * 8 + kt) * B_TH + r * 64 + (((2*c) ^ xr) << 2);
        *(uint4*)dst = val;
    }
}

// ---------------- fp16 mma.sync GEMM: BM=128 BN=128 BK=64, 256 thr, 2 CTAs/SM ----------------
__device__ __forceinline__ void mma_f16(float* c, uint32_t a0, uint32_t a1, uint32_t a2, uint32_t a3,
                                        uint32_t b0, uint32_t b1)
{
    asm volatile(
        "mma.sync.aligned.m16n8k16.row.col.f32.f16.f16.f32 "
        "{%0,%1,%2,%3}, {%4,%5,%6,%7}, {%8,%9}, {%0,%1,%2,%3};"
        : "+f"(c[0]), "+f"(c[1]), "+f"(c[2]), "+f"(c[3])
        : "r"(a0), "r"(a1), "r"(a2), "r"(a3), "r"(b0), "r"(b1));
}

__global__ __launch_bounds__(256, 2)
void gemm_tc(const __half* __restrict__ Wt, const __half* __restrict__ Bt, void* __restrict__ OutV,
             const float* __restrict__ G, const float* __restrict__ Bb,
             const float* __restrict__ Mu, const float* __restrict__ Va, int mode)
{
    extern __shared__ char smraw[];
    __half* smh = (__half*)(smraw + HDR_B);
    const uint32_t sbase = smem_u32(smraw);
    const int tid  = threadIdx.x;
    const int wid  = tid >> 5;
    const int lane = tid & 31;
    const int g    = lane >> 2;
    const int ctib = lane & 3;
    const int wm0  = (wid >> 2) * 64;
    const int wn0  = (wid & 3)  * 32;
    const int mblk = blockIdx.x;
    const int nblk = blockIdx.y;
    const int m0   = mblk * 128;
    const int n0   = nblk * 128;

    if (tid == 0) {
        mbar_init(sbase + 0, 1);
        mbar_init(sbase + 8, 1);
        mbar_init(sbase + 16, 1);
    }
    __syncthreads();

    const __half* Asrc = Wt + (size_t)mblk * 8 * A_TH;
    const __half* Bsrc = Bt + (size_t)nblk * 8 * B_TH;

    if (tid == 0) {
        #pragma unroll
        for (int s = 0; s < 2; s++) {
            uint32_t mb = sbase + s*8;
            uint32_t st = sbase + HDR_B + s*STG_H*2;
            mbar_expect(mb, STG_H*2);
            bulk_cp(st,           Asrc + (size_t)s*A_TH, A_TH*2, mb);
            bulk_cp(st + A_TH*2,  Bsrc + (size_t)s*B_TH, B_TH*2, mb);
        }
    }

    float acc[4][4][4];
    #pragma unroll
    for (int mt = 0; mt < 4; mt++)
        #pragma unroll
        for (int nt = 0; nt < 4; nt++)
            #pragma unroll
            for (int q = 0; q < 4; q++) acc[mt][nt][q] = 0.0f;

    const int gx = (g & 3) << 2;

    for (int kt = 0; kt < 8; kt++) {
        const int s = kt % NST;
        __syncthreads();
        if (tid == 0 && kt + 2 < 8) {
            const int s2 = (kt + 2) % NST;
            uint32_t mb = sbase + s2*8;
            uint32_t st = sbase + HDR_B + s2*STG_H*2;
            mbar_expect(mb, STG_H*2);
            bulk_cp(st,          Asrc + (size_t)(kt+2)*A_TH, A_TH*2, mb);
            bulk_cp(st + A_TH*2, Bsrc + (size_t)(kt+2)*B_TH, B_TH*2, mb);
        }
        mbar_wait(sbase + s*8, (kt / NST) & 1);

        const __half* sA = smh + s*STG_H;
        const __half* sB = sA + A_TH;

        #pragma unroll
        for (int g16 = 0; g16 < 4; g16++) {
            const int ua = ((ctib + 4*g16) ^ gx) * 4;
            uint2 alo[4], ahi[4], bfr[4];
            #pragma unroll
            for (int mt = 0; mt < 4; mt++) {
                const __half* pa = sA + (wm0 + mt*16 + g)*64 + ua;
                alo[mt] = *(const uint2*)pa;
                ahi[mt] = *(const uint2*)(pa + 8*64);
            }
            #pragma unroll
            for (int nt = 0; nt < 4; nt++)
                bfr[nt] = *(const uint2*)(sB + (wn0 + nt*8 + g)*64 + ua);

            #pragma unroll
            for (int mt = 0; mt < 4; mt++)
                #pragma unroll
                for (int nt = 0; nt < 4; nt++)
                    mma_f16(acc[mt][nt],
                            alo[mt].x, ahi[mt].x, alo[mt].y, ahi[mt].y,
                            bfr[nt].x, bfr[nt].y);
        }
    }
    __syncthreads();

    // -------- epilogue: BN + ReLU --------
    if (mode == 0) {
        __half* patch = (__half*)(smraw + HDR_B) + wid * 2304;
        #pragma unroll
        for (int mt = 0; mt < 4; mt++) {
            const int o0 = m0 + wm0 + mt*16 + g;
            const float sc0 = G[o0]   * rsqrtf(Va[o0]   + 1e-5f);
            const float sh0 = Bb[o0]   - Mu[o0]  * sc0;
            const float sc1 = G[o0+8] * rsqrtf(Va[o0+8] + 1e-5f);
            const float sh1 = Bb[o0+8] - Mu[o0+8] * sc1;
            const int ml  = kpos64(mt*16 + g);
            const int mlh = kpos64(mt*16 + g + 8);
            #pragma unroll
            for (int nt = 0; nt < 4; nt++) {
                const int nl = nt*8 + 2*ctib;
                patch[ nl   *72 + ml ] = __float2half_rn(fmaxf(fmaf(acc[mt][nt][0], sc0, sh0), 0.f));
                patch[(nl+1)*72 + ml ] = __float2half_rn(fmaxf(fmaf(acc[mt][nt][1], sc0, sh0), 0.f));
                patch[ nl   *72 + mlh] = __float2half_rn(fmaxf(fmaf(acc[mt][nt][2], sc1, sh1), 0.f));
                patch[(nl+1)*72 + mlh] = __float2half_rn(fmaxf(fmaf(acc[mt][nt][3], sc1, sh1), 0.f));
            }
        }
        __syncwarp();
        const int kt0 = (m0 + wm0) >> 6;
        __half* yb = (__half*)OutV + (size_t)(nblk * 8 + kt0) * B_TH + wn0 * 64;
        #pragma unroll
        for (int rr = 0; rr < 32; rr++) {
            const int off = (((lane >> 1) ^ ((rr & 3) << 2)) << 2) + (lane & 1) * 2;
            *(__half2*)(yb + rr*64 + off) = *(__half2*)(patch + rr*72 + lane*2);
        }
    } else {
        float* patch = (float*)(smraw + HDR_B) + wid * 2304;
        #pragma unroll
        for (int mt = 0; mt < 4; mt++) {
            const int o0 = m0 + wm0 + mt*16 + g;
            const float sc0 = G[o0]   * rsqrtf(Va[o0]   + 1e-5f);
            const float sh0 = Bb[o0]   - Mu[o0]  * sc0;
            const float sc1 = G[o0+8] * rsqrtf(Va[o0+8] + 1e-5f);
            const float sh1 = Bb[o0+8] - Mu[o0+8] * sc1;
            const int ml = mt*16 + g;
            #pragma unroll
            for (int nt = 0; nt < 4; nt++) {
                const int nl = nt*8 + 2*ctib;
                patch[ ml   *36 + nl  ] = fmaxf(fmaf(acc[mt][nt][0], sc0, sh0), 0.f);
                patch[ ml   *36 + nl+1] = fmaxf(fmaf(acc[mt][nt][1], sc0, sh0), 0.f);
                patch[(ml+8)*36 + nl  ] = fmaxf(fmaf(acc[mt][nt][2], sc1, sh1), 0.f);
                patch[(ml+8)*36 + nl+1] = fmaxf(fmaf(acc[mt][nt][3], sc1, sh1), 0.f);
            }
        }
        __syncwarp();
        const int b  = n0 >> 13;
        const int j0 = (n0 & (NPT-1)) + wn0;
        float* ob = (float*)OutV + ((size_t)b * H_ + m0 + wm0) * NPT + j0;
        #pragma unroll
        for (int r = 0; r < 64; r++)
            ob[(size_t)r * NPT + lane] = patch[r*36 + lane];
    }
}

// ---------------- launch ----------------
extern "C" void kernel_launch(void* const* d_in, const int* in_sizes, int n_in,
                              void* d_out, int out_size)
{
    const float* unknown      = (const float*)d_in[0];
    const float* known        = (const float*)d_in[1];
    const float* unknow_feats = (const float*)d_in[2];
    const float* known_feats  = (const float*)d_in[3];
    const float* W1 = (const float*)d_in[4];
    const float* g1 = (const float*)d_in[5];
    const float* b1 = (const float*)d_in[6];
    const float* m1 = (const float*)d_in[7];
    const float* v1 = (const float*)d_in[8];
    const float* W2 = (const float*)d_in[9];
    const float* g2 = (const float*)d_in[10];
    const float* b2 = (const float*)d_in[11];
    const float* m2 = (const float*)d_in[12];
    const float* v2 = (const float*)d_in[13];
    float* out = (float*)d_out;

    __half* Xt;  cudaGetSymbolAddress((void**)&Xt,  g_Xt);
    __half* Yt;  cudaGetSymbolAddress((void**)&Yt,  g_Yt);
    __half* W1t; cudaGetSymbolAddress((void**)&W1t, g_W1t);
    __half* W2t; cudaGetSymbolAddress((void**)&W2t, g_W2t);

    cudaFuncSetAttribute(gemm_tc, cudaFuncAttributeMaxDynamicSharedMemorySize, SMB);

    prep_kernel<<<1024 + 4096 + 16384, 256>>>(W1, W2, known_feats, unknow_feats);
    knn_kernel<<<dim3(NPT/256, B_), 256>>>(unknown, known);
    interp_kernel<<<NTOT/32, 256>>>();

    gemm_tc<<<dim3(4, 512), 256, SMB>>>(W1t, Xt, Yt,  g1, b1, m1, v1, 0);
    gemm_tc<<<dim3(4, 512), 256, SMB>>>(W2t, Yt, out, g2, b2, m2, v2, 1);

    (void)in_sizes; (void)n_in; (void)out_size;
}